// round 1
// baseline (speedup 1.0000x reference)
#include <cuda_runtime.h>
#include <math.h>

// ---------------- problem constants ----------------
#define NB 32          // batch
#define C_EMB 128      // embed channels
#define HID 32         // CBAM hidden
#define KIDX 100       // gathered indices per batch

#define HW_0 6400
#define HW_1 1600
#define HW_2 400
#define SIDE0 80
#define SIDE1 40
#define SIDE2 20

// ---------------- device scratch (no cudaMalloc allowed) ----------------
__device__ float g_y0s0[(size_t)NB * HW_0 * C_EMB];   // [b][hw][c]
__device__ float g_y0s1[(size_t)NB * HW_1 * C_EMB];
__device__ float g_y0s2[(size_t)NB * HW_2 * C_EMB];

__device__ unsigned g_maxenc[3 * NB * C_EMB];
__device__ float    g_sum[3 * NB * C_EMB];
__device__ float    g_gate[3 * NB * C_EMB];

__device__ float g_smx0[NB * HW_0], g_sav0[NB * HW_0], g_s0[NB * HW_0];
__device__ float g_smx1[NB * HW_1], g_sav1[NB * HW_1], g_s1[NB * HW_1];
__device__ float g_smx2[NB * HW_2], g_sav2[NB * HW_2], g_s2[NB * HW_2];

// ---------------- helpers ----------------
__device__ __forceinline__ unsigned long long pk2(float x, float y) {
    unsigned long long r;
    asm("mov.b64 %0,{%1,%2};" : "=l"(r) : "f"(x), "f"(y));
    return r;
}
__device__ __forceinline__ void upk2(unsigned long long v, float& x, float& y) {
    asm("mov.b64 {%0,%1},%2;" : "=f"(x), "=f"(y) : "l"(v));
}
__device__ __forceinline__ void ffma2(unsigned long long& d, unsigned long long a,
                                      unsigned long long b) {
    asm("fma.rn.f32x2 %0,%1,%2,%0;" : "+l"(d) : "l"(a), "l"(b));
}

__device__ __forceinline__ unsigned encf(float f) {
    unsigned u = __float_as_uint(f);
    return (u & 0x80000000u) ? ~u : (u | 0x80000000u);
}
__device__ __forceinline__ float decf(unsigned e) {
    return (e & 0x80000000u) ? __uint_as_float(e & 0x7FFFFFFFu)
                             : __uint_as_float(~e);
}
__device__ __forceinline__ float sigmoidf_(float x) {
    return 1.0f / (1.0f + __expf(-x));
}

// ---------------- init stats ----------------
__global__ void init_stats() {
    int i = blockIdx.x * blockDim.x + threadIdx.x;
    if (i < 3 * NB * C_EMB) { g_maxenc[i] = 0u; g_sum[i] = 0.0f; }
}

// ---------------- neck GEMM: Y[b][hw][c] = sum_k W[c][k] * X[b][k][hw] + bias[c] ----------------
// Block tile: 128(M=c) x 128(N=hw), 256 threads, per-thread 8m x 8n with packed f32x2.
template <int CIN>
__global__ void __launch_bounds__(256, 2)
neck_gemm(const float* __restrict__ X, const float* __restrict__ Wt,
          const float* __restrict__ bias, float* __restrict__ Y, int HW) {
    __shared__ float Ws[16][128];       // Ws[kk][m]
    __shared__ float Xs[16][128];       // Xs[kk][n]

    const int b   = blockIdx.y;
    const int hw0 = blockIdx.x * 128;
    const int tid = threadIdx.x;
    const int tx  = tid >> 4;   // 0..15  (n dim)
    const int ty  = tid & 15;   // 0..15  (m dim)

    const float* Xb = X + (size_t)b * CIN * HW;

    unsigned long long acc[4][8];       // [m-pair][n]
#pragma unroll
    for (int p = 0; p < 4; p++)
#pragma unroll
        for (int n = 0; n < 8; n++) acc[p][n] = 0ull;

    const int wm = tid & 127;           // W-load row (m)
    const int wq = tid >> 7;            // 0/1
    const int xk = tid >> 4;            // X-load row (kk) 0..15
    const int xn = (tid & 15) * 4;      // X-load col base

    for (int k0 = 0; k0 < CIN; k0 += 16) {
        // load W tile (k contiguous in gmem -> scatter to Ws[kk][m])
#pragma unroll
        for (int r = 0; r < 2; r++) {
            int kq = wq + r * 2;                      // 0..3
            float4 w4 = *(const float4*)&Wt[(size_t)wm * CIN + k0 + kq * 4];
            Ws[kq * 4 + 0][wm] = w4.x;
            Ws[kq * 4 + 1][wm] = w4.y;
            Ws[kq * 4 + 2][wm] = w4.z;
            Ws[kq * 4 + 3][wm] = w4.w;
        }
        // load X tile (hw contiguous -> coalesced)
        const float* src = Xb + (size_t)(k0 + xk) * HW;
#pragma unroll
        for (int r = 0; r < 2; r++) {
            int n  = xn + r * 64;
            int hw = hw0 + n;
            float4 v;
            if (hw + 4 <= HW) v = *(const float4*)(src + hw);
            else              v = make_float4(0.f, 0.f, 0.f, 0.f);
            *(float4*)&Xs[xk][n] = v;
        }
        __syncthreads();

#pragma unroll
        for (int kk = 0; kk < 16; kk++) {
            const float* wr = &Ws[kk][ty * 8];
            unsigned long long av[4];
            av[0] = *(const unsigned long long*)(wr + 0);
            av[1] = *(const unsigned long long*)(wr + 2);
            av[2] = *(const unsigned long long*)(wr + 4);
            av[3] = *(const unsigned long long*)(wr + 6);
            const float* xr = &Xs[kk][tx * 8];
            float4 xb0 = *(const float4*)(xr);
            float4 xb1 = *(const float4*)(xr + 4);
            unsigned long long pb[8];
            pb[0] = pk2(xb0.x, xb0.x); pb[1] = pk2(xb0.y, xb0.y);
            pb[2] = pk2(xb0.z, xb0.z); pb[3] = pk2(xb0.w, xb0.w);
            pb[4] = pk2(xb1.x, xb1.x); pb[5] = pk2(xb1.y, xb1.y);
            pb[6] = pk2(xb1.z, xb1.z); pb[7] = pk2(xb1.w, xb1.w);
#pragma unroll
            for (int n = 0; n < 8; n++)
#pragma unroll
                for (int p = 0; p < 4; p++) ffma2(acc[p][n], av[p], pb[n]);
        }
        __syncthreads();
    }

    // epilogue: add bias, store NHWC
    float br[8];
#pragma unroll
    for (int i = 0; i < 8; i++) br[i] = bias[ty * 8 + i];

#pragma unroll
    for (int n = 0; n < 8; n++) {
        int hw = hw0 + tx * 8 + n;
        if (hw >= HW) continue;
        float m[8];
        upk2(acc[0][n], m[0], m[1]);
        upk2(acc[1][n], m[2], m[3]);
        upk2(acc[2][n], m[4], m[5]);
        upk2(acc[3][n], m[6], m[7]);
        float4 o0 = make_float4(m[0] + br[0], m[1] + br[1], m[2] + br[2], m[3] + br[3]);
        float4 o1 = make_float4(m[4] + br[4], m[5] + br[5], m[6] + br[6], m[7] + br[7]);
        float* dst = Y + ((size_t)b * HW + hw) * C_EMB + ty * 8;
        *(float4*)dst       = o0;
        *((float4*)dst + 1) = o1;
    }
}

// ---------------- CAM stats: per (b,c) max & sum over HW ----------------
__global__ void cam_stats(const float* __restrict__ Y, int HW, int scale) {
    const int b  = blockIdx.y;
    const int c  = threadIdx.x;           // 128
    const int h0 = blockIdx.x * 256;
    const int n  = min(256, HW - h0);
    const float* base = Y + ((size_t)b * HW + h0) * C_EMB + c;
    float mx = -3.4e38f, sm = 0.0f;
    for (int i = 0; i < n; i++) {
        float v = base[(size_t)i * C_EMB];
        mx = fmaxf(mx, v);
        sm += v;
    }
    int o = (scale * NB + b) * C_EMB + c;
    atomicMax(&g_maxenc[o], encf(mx));
    atomicAdd(&g_sum[o], sm);
}

// ---------------- gate: tiny shared MLP + sigmoid ----------------
__global__ void gate_kernel(const float* __restrict__ w1, const float* __restrict__ b1,
                            const float* __restrict__ w2, const float* __restrict__ b2,
                            int scale, int HW) {
    __shared__ float vmx[C_EMB], vav[C_EMB], hmx[HID], hav[HID];
    const int b = blockIdx.x;
    const int c = threadIdx.x;            // 128
    const int o = (scale * NB + b) * C_EMB + c;
    vmx[c] = decf(g_maxenc[o]);
    vav[c] = g_sum[o] * (1.0f / (float)HW);
    __syncthreads();
    if (c < HID) {
        float s1 = b1[c], s2 = b1[c];
        for (int k = 0; k < C_EMB; k++) {
            float w = w1[c * C_EMB + k];
            s1 += w * vmx[k];
            s2 += w * vav[k];
        }
        hmx[c] = fmaxf(s1, 0.0f);
        hav[c] = fmaxf(s2, 0.0f);
    }
    __syncthreads();
    float o1 = b2[c], o2 = b2[c];
    for (int k = 0; k < HID; k++) {
        float w = w2[c * HID + k];
        o1 += w * hmx[k];
        o2 += w * hav[k];
    }
    g_gate[o] = sigmoidf_(o1 + o2);
}

// ---------------- SAM stats: per pixel max/mean over c of gate*y ----------------
__global__ void sam_stats(const float* __restrict__ Y, float* __restrict__ smx,
                          float* __restrict__ sav, int HW, int scale) {
    __shared__ float gsh[C_EMB];
    const int tid  = threadIdx.x;         // 256
    const int gw   = (blockIdx.x * 256 + tid) >> 5;   // global warp == pixel
    const int lane = tid & 31;
    const int b    = gw / HW;
    const int hw   = gw - b * HW;
    if (tid < C_EMB) gsh[tid] = g_gate[(scale * NB + b) * C_EMB + tid];
    __syncthreads();
    float4 v = *(const float4*)&Y[((size_t)b * HW + hw) * C_EMB + lane * 4];
    float4 g = *(const float4*)&gsh[lane * 4];
    float a0 = v.x * g.x, a1 = v.y * g.y, a2 = v.z * g.z, a3 = v.w * g.w;
    float mx = fmaxf(fmaxf(a0, a1), fmaxf(a2, a3));
    float sm = a0 + a1 + a2 + a3;
#pragma unroll
    for (int o = 16; o; o >>= 1) {
        mx = fmaxf(mx, __shfl_xor_sync(0xFFFFFFFFu, mx, o));
        sm += __shfl_xor_sync(0xFFFFFFFFu, sm, o);
    }
    if (lane == 0) {
        smx[gw] = mx;
        sav[gw] = sm * (1.0f / (float)C_EMB);
    }
}

// ---------------- 7x7 conv on [max, mean] channel maps ----------------
__global__ void conv7(const float* __restrict__ smx, const float* __restrict__ sav,
                      const float* __restrict__ sw, float* __restrict__ S, int SIDE) {
    __shared__ float w[98];
    const int tid = threadIdx.x;          // 256
    if (tid < 98) w[tid] = sw[tid];       // [0..48] max-ch, [49..97] mean-ch
    __syncthreads();
    const int HW = SIDE * SIDE;
    const int p  = blockIdx.x * 256 + tid;
    if (p >= NB * HW) return;
    const int b  = p / HW, hw = p - b * HW;
    const int y  = hw / SIDE, x = hw - y * SIDE;
    const float* mp = smx + (size_t)b * HW;
    const float* ap = sav + (size_t)b * HW;
    float acc = 0.0f;
#pragma unroll
    for (int dy = -3; dy <= 3; dy++) {
        int yy = y + dy;
        if (yy < 0 || yy >= SIDE) continue;
#pragma unroll
        for (int dx = -3; dx <= 3; dx++) {
            int xx = x + dx;
            if (xx < 0 || xx >= SIDE) continue;
            int wi = (dy + 3) * 7 + (dx + 3);
            int q  = yy * SIDE + xx;
            acc += mp[q] * w[wi] + ap[q] * w[49 + wi];
        }
    }
    S[p] = acc;
}

// ---------------- gather: out[row][c] = y0 * (1 + gate*sigmoid(s)) ----------------
__global__ void gather_out(const int* __restrict__ idx, float* __restrict__ out) {
    const int row = blockIdx.x;           // 0..3199
    const int c   = threadIdx.x;          // 128
    const int b   = row / KIDX;
    const int id  = idx[row];
    const float* Y; const float* S; int HW, scale, p;
    if (id < HW_0)              { Y = g_y0s0; S = g_s0; HW = HW_0; scale = 0; p = id; }
    else if (id < HW_0 + HW_1)  { Y = g_y0s1; S = g_s1; HW = HW_1; scale = 1; p = id - HW_0; }
    else                        { Y = g_y0s2; S = g_s2; HW = HW_2; scale = 2; p = id - (HW_0 + HW_1); }
    float y   = Y[((size_t)b * HW + p) * C_EMB + c];
    float g   = g_gate[(scale * NB + b) * C_EMB + c];
    float sig = sigmoidf_(S[b * HW + p]);
    out[(size_t)row * C_EMB + c] = y * (1.0f + g * sig);
}

// ---------------- launch ----------------
extern "C" void kernel_launch(void* const* d_in, const int* in_sizes, int n_in,
                              void* d_out, int out_size) {
    const float* x0   = (const float*)d_in[0];
    const float* x1   = (const float*)d_in[1];
    const float* x2   = (const float*)d_in[2];
    const float* yolo = (const float*)d_in[3];
    const int*   ridx = (const int*)d_in[4];
    const float* nw0 = (const float*)d_in[5];
    const float* nb0 = (const float*)d_in[6];
    const float* nw1 = (const float*)d_in[7];
    const float* nb1 = (const float*)d_in[8];
    const float* nw2 = (const float*)d_in[9];
    const float* nb2 = (const float*)d_in[10];
    const float* cw1[3] = {(const float*)d_in[11], (const float*)d_in[16], (const float*)d_in[21]};
    const float* cb1[3] = {(const float*)d_in[12], (const float*)d_in[17], (const float*)d_in[22]};
    const float* cw2[3] = {(const float*)d_in[13], (const float*)d_in[18], (const float*)d_in[23]};
    const float* cb2[3] = {(const float*)d_in[14], (const float*)d_in[19], (const float*)d_in[24]};
    const float* csw[3] = {(const float*)d_in[15], (const float*)d_in[20], (const float*)d_in[25]};

    float* out = (float*)d_out;
    const int yolo_n = NB * 8400 * 6;
    const int emb_n  = NB * KIDX * C_EMB;
    float* emb_out = out;
    if (out_size >= yolo_n + emb_n) {
        cudaMemcpyAsync(out, yolo, (size_t)in_sizes[3] * sizeof(float),
                        cudaMemcpyDeviceToDevice, 0);
        emb_out = out + yolo_n;
    }

    // resolve device-scratch addresses (host side; fine for graph capture)
    float *y0p, *y1p, *y2p;
    cudaGetSymbolAddress((void**)&y0p, g_y0s0);
    cudaGetSymbolAddress((void**)&y1p, g_y0s1);
    cudaGetSymbolAddress((void**)&y2p, g_y0s2);
    float *smx0p, *sav0p, *s0p, *smx1p, *sav1p, *s1p, *smx2p, *sav2p, *s2p;
    cudaGetSymbolAddress((void**)&smx0p, g_smx0);
    cudaGetSymbolAddress((void**)&sav0p, g_sav0);
    cudaGetSymbolAddress((void**)&s0p,   g_s0);
    cudaGetSymbolAddress((void**)&smx1p, g_smx1);
    cudaGetSymbolAddress((void**)&sav1p, g_sav1);
    cudaGetSymbolAddress((void**)&s1p,   g_s1);
    cudaGetSymbolAddress((void**)&smx2p, g_smx2);
    cudaGetSymbolAddress((void**)&sav2p, g_sav2);
    cudaGetSymbolAddress((void**)&s2p,   g_s2);

    init_stats<<<(3 * NB * C_EMB + 255) / 256, 256>>>();

    // scale 0
    neck_gemm<256><<<dim3((HW_0 + 127) / 128, NB), 256>>>(x0, nw0, nb0, y0p, HW_0);
    cam_stats<<<dim3((HW_0 + 255) / 256, NB), 128>>>(y0p, HW_0, 0);
    // scale 1
    neck_gemm<512><<<dim3((HW_1 + 127) / 128, NB), 256>>>(x1, nw1, nb1, y1p, HW_1);
    cam_stats<<<dim3((HW_1 + 255) / 256, NB), 128>>>(y1p, HW_1, 1);
    // scale 2
    neck_gemm<1024><<<dim3((HW_2 + 127) / 128, NB), 256>>>(x2, nw2, nb2, y2p, HW_2);
    cam_stats<<<dim3((HW_2 + 255) / 256, NB), 128>>>(y2p, HW_2, 2);

    gate_kernel<<<NB, 128>>>(cw1[0], cb1[0], cw2[0], cb2[0], 0, HW_0);
    gate_kernel<<<NB, 128>>>(cw1[1], cb1[1], cw2[1], cb2[1], 1, HW_1);
    gate_kernel<<<NB, 128>>>(cw1[2], cb1[2], cw2[2], cb2[2], 2, HW_2);

    sam_stats<<<NB * HW_0 / 8, 256>>>(y0p, smx0p, sav0p, HW_0, 0);
    sam_stats<<<NB * HW_1 / 8, 256>>>(y1p, smx1p, sav1p, HW_1, 1);
    sam_stats<<<NB * HW_2 / 8, 256>>>(y2p, smx2p, sav2p, HW_2, 2);

    conv7<<<(NB * HW_0 + 255) / 256, 256>>>(smx0p, sav0p, csw[0], s0p, SIDE0);
    conv7<<<(NB * HW_1 + 255) / 256, 256>>>(smx1p, sav1p, csw[1], s1p, SIDE1);
    conv7<<<(NB * HW_2 + 255) / 256, 256>>>(smx2p, sav2p, csw[2], s2p, SIDE2);

    gather_out<<<NB * KIDX, 128>>>(ridx, emb_out);
}

// round 3
// speedup vs baseline: 1.6111x; 1.6111x over previous
#include <cuda_runtime.h>
#include <cuda_bf16.h>
#include <cstdint>
#include <math.h>

// ---------------- problem constants ----------------
#define NB 32
#define C_EMB 128
#define HID 32
#define KIDX 100

#define HW_0 6400
#define HW_1 1600
#define HW_2 400
#define SIDE0 80
#define SIDE1 40
#define SIDE2 20

// ---------------- device scratch ----------------
__device__ __align__(128) float g_y0s0[(size_t)NB * HW_0 * C_EMB];
__device__ __align__(128) float g_y0s1[(size_t)NB * HW_1 * C_EMB];
__device__ __align__(128) float g_y0s2[(size_t)NB * HW_2 * C_EMB];

// converted weights: [m][k] bf16 hi/lo
__device__ __align__(128) __nv_bfloat16 g_wh0[C_EMB * 256],  g_wl0[C_EMB * 256];
__device__ __align__(128) __nv_bfloat16 g_wh1[C_EMB * 512],  g_wl1[C_EMB * 512];
__device__ __align__(128) __nv_bfloat16 g_wh2[C_EMB * 1024], g_wl2[C_EMB * 1024];

__device__ unsigned g_maxenc[3 * NB * C_EMB];
__device__ float    g_sum[3 * NB * C_EMB];
__device__ float    g_gate[3 * NB * C_EMB];

__device__ float g_smx0[NB * HW_0], g_sav0[NB * HW_0], g_s0[NB * HW_0];
__device__ float g_smx1[NB * HW_1], g_sav1[NB * HW_1], g_s1[NB * HW_1];
__device__ float g_smx2[NB * HW_2], g_sav2[NB * HW_2], g_s2[NB * HW_2];

// ---------------- helpers ----------------
__device__ __forceinline__ uint32_t smem_to_u32(const void* p) {
    uint32_t a;
    asm("{ .reg .u64 t; cvta.to.shared.u64 t, %1; cvt.u32.u64 %0, t; }" : "=r"(a) : "l"(p));
    return a;
}
__device__ __forceinline__ void ldsm_x4(uint32_t* r, uint32_t addr) {
    asm volatile("ldmatrix.sync.aligned.m8n8.x4.shared.b16 {%0,%1,%2,%3}, [%4];"
                 : "=r"(r[0]), "=r"(r[1]), "=r"(r[2]), "=r"(r[3]) : "r"(addr));
}
__device__ __forceinline__ void ldsm_x4_t(uint32_t* r, uint32_t addr) {
    asm volatile("ldmatrix.sync.aligned.m8n8.x4.trans.shared.b16 {%0,%1,%2,%3}, [%4];"
                 : "=r"(r[0]), "=r"(r[1]), "=r"(r[2]), "=r"(r[3]) : "r"(addr));
}
__device__ __forceinline__ void mma_bf16(float* d, const uint32_t* a, const uint32_t* b) {
    asm volatile("mma.sync.aligned.m16n8k16.row.col.f32.bf16.bf16.f32 "
                 "{%0,%1,%2,%3}, {%4,%5,%6,%7}, {%8,%9}, {%0,%1,%2,%3};"
                 : "+f"(d[0]), "+f"(d[1]), "+f"(d[2]), "+f"(d[3])
                 : "r"(a[0]), "r"(a[1]), "r"(a[2]), "r"(a[3]), "r"(b[0]), "r"(b[1]));
}
__device__ __forceinline__ unsigned encf(float f) {
    unsigned u = __float_as_uint(f);
    return (u & 0x80000000u) ? ~u : (u | 0x80000000u);
}
__device__ __forceinline__ float decf(unsigned e) {
    return (e & 0x80000000u) ? __uint_as_float(e & 0x7FFFFFFFu) : __uint_as_float(~e);
}
__device__ __forceinline__ float sigmoidf_(float x) { return 1.0f / (1.0f + __expf(-x)); }

// ---------------- init stats ----------------
__global__ void init_stats() {
    int i = blockIdx.x * blockDim.x + threadIdx.x;
    if (i < 3 * NB * C_EMB) { g_maxenc[i] = 0u; g_sum[i] = 0.0f; }
}

// ---------------- weight conversion: fp32 -> bf16 hi/lo ----------------
__global__ void convert_w(const float* __restrict__ W, __nv_bfloat16* __restrict__ Wh,
                          __nv_bfloat16* __restrict__ Wl, int n) {
    int i = blockIdx.x * 256 + threadIdx.x;
    if (i >= n) return;
    float v = W[i];
    __nv_bfloat16 h = __float2bfloat16(v);
    __nv_bfloat16 l = __float2bfloat16(v - __bfloat162float(h));
    Wh[i] = h; Wl[i] = l;
}

// ---------------- HMMA GEMM with fused fp32->bf16 split conversion ----------------
// Y[b][hw][m] = sum_k W[m][k] * X[b][k][hw] + bias[m]
// CTA tile: 128 hw (M) x 128 ch (N); K-chunk 64.
// smem: XH[64][128]bf16(16K) XL(16K) WH[128][64]bf16(16K) WL(16K), then reuse as C[128][128]f32;
//       bias[128]f32 at 65536.
static constexpr int SM_XH = 0;
static constexpr int SM_XL = 16384;
static constexpr int SM_WH = 32768;
static constexpr int SM_WL = 49152;
static constexpr int SM_BIAS = 65536;
static constexpr int SMEM_GEMM = 65536 + 512;

template <int CIN>
__global__ void __launch_bounds__(256)
tc_gemm(const float* __restrict__ X,
        const __nv_bfloat16* __restrict__ Wh, const __nv_bfloat16* __restrict__ Wl,
        const float* __restrict__ bias, float* __restrict__ Y, int HW, int scale) {
    extern __shared__ __align__(128) char smem[];
    const uint32_t sb = smem_to_u32(smem);
    const int tid  = threadIdx.x;
    const int lane = tid & 31;
    const int wid  = tid >> 5;
    const int wm   = wid & 3;     // 0..3  (m: 32 rows each)
    const int wn   = wid >> 2;    // 0..1  (n: 64 cols each)
    const int b    = blockIdx.y;
    const int hw0  = blockIdx.x * 128;

    int nvalid = HW - hw0; if (nvalid > 128) nvalid = 128;

    // preload bias to smem
    if (tid < 32) ((float4*)(smem + SM_BIAS))[tid] = ((const float4*)bias)[tid];

    // ldmatrix per-thread address components
    const int ti = lane & 7;
    const int gq = lane >> 3;           // 0..3 quadrant group
    // A (trans, from [k][hw] tiles): quadrant -> m halves / k halves
    const int aKrow = ((gq >> 1) << 3) + ti;    // k row within k16 (0..15)
    const int aMsel = (gq & 1) << 3;            // +0 / +8 on m
    // B (non-trans, from [n][k] tiles): quadrant -> n halves / k halves
    const int bKsel = gq & 1;                   // k 8-seg within k16
    const int bNrow = ((gq >> 1) << 3) + ti;    // n row offset within n16

    uint32_t offA[2];   // per m16 tile, excluding kbase term and mat base
#pragma unroll
    for (int mt = 0; mt < 2; mt++) {
        int m0 = wm * 32 + mt * 16 + aMsel;
        offA[mt] = (uint32_t)(aKrow * 256 + ((((m0 >> 3) ^ (aKrow & 7)) << 4)));
    }

    float acc[2][8][4];
#pragma unroll
    for (int mt = 0; mt < 2; mt++)
#pragma unroll
        for (int nt = 0; nt < 8; nt++)
#pragma unroll
            for (int r = 0; r < 4; r++) acc[mt][nt][r] = 0.0f;

    // X load mapping: thread -> k-row r (0..63), 8 float4 cols
    const int xr  = tid >> 2;            // k row
    const int xc0 = tid & 3;             // float4 col base (steps of 4)
    const float* xsrc = X + ((size_t)b * CIN) * HW + hw0;

    constexpr int NCHUNK = CIN / 64;
    for (int ck = 0; ck < NCHUNK; ck++) {
        if (ck > 0) __syncthreads();
        const int k0 = ck * 64;
        // ---- load + convert X tile: [64 k][128 hw] fp32 -> bf16 hi/lo swizzled ----
        {
            const float* row = xsrc + (size_t)(k0 + xr) * HW;
#pragma unroll
            for (int i = 0; i < 8; i++) {
                int c4 = xc0 + i * 4;             // 0..31
                int hwb = c4 * 4;
                float4 v = (hw0 + hwb < HW) ? *(const float4*)(row + hwb)
                                            : make_float4(0.f, 0.f, 0.f, 0.f);
                __nv_bfloat16 h0 = __float2bfloat16(v.x);
                __nv_bfloat16 h1 = __float2bfloat16(v.y);
                __nv_bfloat16 h2 = __float2bfloat16(v.z);
                __nv_bfloat16 h3 = __float2bfloat16(v.w);
                __nv_bfloat16 l0 = __float2bfloat16(v.x - __bfloat162float(h0));
                __nv_bfloat16 l1 = __float2bfloat16(v.y - __bfloat162float(h1));
                __nv_bfloat16 l2 = __float2bfloat16(v.z - __bfloat162float(h2));
                __nv_bfloat16 l3 = __float2bfloat16(v.w - __bfloat162float(h3));
                uint2 ph = make_uint2(
                    (uint32_t)__bfloat16_as_ushort(h0) | ((uint32_t)__bfloat16_as_ushort(h1) << 16),
                    (uint32_t)__bfloat16_as_ushort(h2) | ((uint32_t)__bfloat16_as_ushort(h3) << 16));
                uint2 pl = make_uint2(
                    (uint32_t)__bfloat16_as_ushort(l0) | ((uint32_t)__bfloat16_as_ushort(l1) << 16),
                    (uint32_t)__bfloat16_as_ushort(l2) | ((uint32_t)__bfloat16_as_ushort(l3) << 16));
                int seg  = c4 >> 1;               // 16B segment (0..15)
                int half = (c4 & 1) * 8;
                uint32_t off = (uint32_t)(xr * 256 + (((seg ^ (xr & 7)) << 4)) + half);
                *(uint2*)(smem + SM_XH + off) = ph;
                *(uint2*)(smem + SM_XL + off) = pl;
            }
        }
        // ---- load W tiles: [128 n][64 k] bf16 swizzled ----
        {
#pragma unroll
            for (int i = 0; i < 4; i++) {
                int idx = tid + i * 256;          // 0..1023
                int n   = idx >> 3;
                int seg = idx & 7;
                uint32_t off = (uint32_t)(n * 128 + ((seg ^ (n & 7)) << 4));
                *(float4*)(smem + SM_WH + off) =
                    *(const float4*)(Wh + (size_t)n * CIN + k0 + seg * 8);
                *(float4*)(smem + SM_WL + off) =
                    *(const float4*)(Wl + (size_t)n * CIN + k0 + seg * 8);
            }
        }
        __syncthreads();

        // ---- MMA: 4 k16 steps ----
#pragma unroll
        for (int ks = 0; ks < 4; ks++) {
            const uint32_t kb256 = (uint32_t)(ks * 16 * 256);
            uint32_t ah[2][4], al[2][4];
            ldsm_x4_t(ah[0], sb + SM_XH + kb256 + offA[0]);
            ldsm_x4_t(ah[1], sb + SM_XH + kb256 + offA[1]);
            ldsm_x4_t(al[0], sb + SM_XL + kb256 + offA[0]);
            ldsm_x4_t(al[1], sb + SM_XL + kb256 + offA[1]);
#pragma unroll
            for (int np = 0; np < 4; np++) {
                int nrow = wn * 64 + np * 16 + bNrow;
                int kseg = ks * 2 + bKsel;                 // 0..7
                uint32_t boff = (uint32_t)(nrow * 128 + (((kseg ^ (nrow & 7)) << 4)));
                uint32_t bh[4], bl[4];
                ldsm_x4(bh, sb + SM_WH + boff);
                ldsm_x4(bl, sb + SM_WL + boff);
#pragma unroll
                for (int mt = 0; mt < 2; mt++)
#pragma unroll
                    for (int s = 0; s < 2; s++)
                        mma_bf16(acc[mt][np * 2 + s], ah[mt], &bh[s * 2]);
#pragma unroll
                for (int mt = 0; mt < 2; mt++)
#pragma unroll
                    for (int s = 0; s < 2; s++)
                        mma_bf16(acc[mt][np * 2 + s], ah[mt], &bl[s * 2]);
#pragma unroll
                for (int mt = 0; mt < 2; mt++)
#pragma unroll
                    for (int s = 0; s < 2; s++)
                        mma_bf16(acc[mt][np * 2 + s], al[mt], &bh[s * 2]);
            }
        }
    }
    __syncthreads();

    // ---- stage C through smem (reuse tile region): Cs[128 hw][128 ch] fp32 ----
    float* Cs = (float*)smem;
#pragma unroll
    for (int mt = 0; mt < 2; mt++) {
#pragma unroll
        for (int nt = 0; nt < 8; nt++) {
            int r0 = wm * 32 + mt * 16 + (lane >> 2);
            int c0 = wn * 64 + nt * 8 + (lane & 3) * 2;
            *(float2*)&Cs[r0 * 128 + c0]       = make_float2(acc[mt][nt][0], acc[mt][nt][1]);
            *(float2*)&Cs[(r0 + 8) * 128 + c0] = make_float2(acc[mt][nt][2], acc[mt][nt][3]);
        }
    }
    __syncthreads();

    const float* bsm = (const float*)(smem + SM_BIAS);
    // coalesced Y store with bias
    float* yb = Y + ((size_t)b * HW + hw0) * C_EMB;
    for (int idx = tid; idx < nvalid * 32; idx += 256) {
        int r  = idx >> 5;
        int c4 = idx & 31;
        float4 v = ((const float4*)(Cs + r * 128))[c4];
        float4 bv = ((const float4*)bsm)[c4];
        v.x += bv.x; v.y += bv.y; v.z += bv.z; v.w += bv.w;
        ((float4*)(yb + (size_t)r * C_EMB))[c4] = v;
    }
    // CAM stats: thread = channel, conflict-free row scans
    if (tid < 128) {
        float bv = bsm[tid];
        float mx = -3.4e38f, sm = 0.0f;
        for (int r = 0; r < nvalid; r++) {
            float v = Cs[r * 128 + tid] + bv;
            mx = fmaxf(mx, v);
            sm += v;
        }
        int o = (scale * NB + b) * C_EMB + tid;
        atomicMax(&g_maxenc[o], encf(mx));
        atomicAdd(&g_sum[o], sm);
    }
}

// ---------------- gate: tiny shared MLP + sigmoid ----------------
__global__ void gate_kernel(const float* __restrict__ w1, const float* __restrict__ b1,
                            const float* __restrict__ w2, const float* __restrict__ b2,
                            int scale, int HW) {
    __shared__ float vmx[C_EMB], vav[C_EMB], hmx[HID], hav[HID];
    const int b = blockIdx.x;
    const int c = threadIdx.x;
    const int o = (scale * NB + b) * C_EMB + c;
    vmx[c] = decf(g_maxenc[o]);
    vav[c] = g_sum[o] * (1.0f / (float)HW);
    __syncthreads();
    if (c < HID) {
        float s1 = b1[c], s2 = b1[c];
        for (int k = 0; k < C_EMB; k++) {
            float w = w1[c * C_EMB + k];
            s1 += w * vmx[k];
            s2 += w * vav[k];
        }
        hmx[c] = fmaxf(s1, 0.0f);
        hav[c] = fmaxf(s2, 0.0f);
    }
    __syncthreads();
    float o1 = b2[c], o2 = b2[c];
    for (int k = 0; k < HID; k++) {
        float w = w2[c * HID + k];
        o1 += w * hmx[k];
        o2 += w * hav[k];
    }
    g_gate[o] = sigmoidf_(o1 + o2);
}

// ---------------- SAM stats ----------------
__global__ void sam_stats(const float* __restrict__ Y, float* __restrict__ smx,
                          float* __restrict__ sav, int HW, int scale) {
    __shared__ float gsh[C_EMB];
    const int tid  = threadIdx.x;
    const int gw   = (blockIdx.x * 256 + tid) >> 5;
    const int lane = tid & 31;
    const int b    = gw / HW;
    const int hw   = gw - b * HW;
    if (tid < C_EMB) gsh[tid] = g_gate[(scale * NB + b) * C_EMB + tid];
    __syncthreads();
    float4 v = *(const float4*)&Y[((size_t)b * HW + hw) * C_EMB + lane * 4];
    float4 g = *(const float4*)&gsh[lane * 4];
    float a0 = v.x * g.x, a1 = v.y * g.y, a2 = v.z * g.z, a3 = v.w * g.w;
    float mx = fmaxf(fmaxf(a0, a1), fmaxf(a2, a3));
    float sm = a0 + a1 + a2 + a3;
#pragma unroll
    for (int o = 16; o; o >>= 1) {
        mx = fmaxf(mx, __shfl_xor_sync(0xFFFFFFFFu, mx, o));
        sm += __shfl_xor_sync(0xFFFFFFFFu, sm, o);
    }
    if (lane == 0) {
        smx[gw] = mx;
        sav[gw] = sm * (1.0f / (float)C_EMB);
    }
}

// ---------------- 7x7 conv on [max, mean] ----------------
__global__ void conv7(const float* __restrict__ smx, const float* __restrict__ sav,
                      const float* __restrict__ sw, float* __restrict__ S, int SIDE) {
    __shared__ float w[98];
    const int tid = threadIdx.x;
    if (tid < 98) w[tid] = sw[tid];
    __syncthreads();
    const int HW = SIDE * SIDE;
    const int p  = blockIdx.x * 256 + tid;
    if (p >= NB * HW) return;
    const int b  = p / HW, hw = p - b * HW;
    const int y  = hw / SIDE, x = hw - y * SIDE;
    const float* mp = smx + (size_t)b * HW;
    const float* ap = sav + (size_t)b * HW;
    float acc = 0.0f;
#pragma unroll
    for (int dy = -3; dy <= 3; dy++) {
        int yy = y + dy;
        if (yy < 0 || yy >= SIDE) continue;
#pragma unroll
        for (int dx = -3; dx <= 3; dx++) {
            int xx = x + dx;
            if (xx < 0 || xx >= SIDE) continue;
            int wi = (dy + 3) * 7 + (dx + 3);
            int q  = yy * SIDE + xx;
            acc += mp[q] * w[wi] + ap[q] * w[49 + wi];
        }
    }
    S[p] = acc;
}

// ---------------- gather ----------------
__global__ void gather_out(const int* __restrict__ idx, float* __restrict__ out) {
    const int row = blockIdx.x;
    const int c   = threadIdx.x;
    const int b   = row / KIDX;
    const int id  = idx[row];
    const float* Y; const float* S; int HW, scale, p;
    if (id < HW_0)              { Y = g_y0s0; S = g_s0; HW = HW_0; scale = 0; p = id; }
    else if (id < HW_0 + HW_1)  { Y = g_y0s1; S = g_s1; HW = HW_1; scale = 1; p = id - HW_0; }
    else                        { Y = g_y0s2; S = g_s2; HW = HW_2; scale = 2; p = id - (HW_0 + HW_1); }
    float y   = Y[((size_t)b * HW + p) * C_EMB + c];
    float g   = g_gate[(scale * NB + b) * C_EMB + c];
    float sig = sigmoidf_(S[b * HW + p]);
    out[(size_t)row * C_EMB + c] = y * (1.0f + g * sig);
}

// ---------------- launch ----------------
extern "C" void kernel_launch(void* const* d_in, const int* in_sizes, int n_in,
                              void* d_out, int out_size) {
    const float* x0   = (const float*)d_in[0];
    const float* x1   = (const float*)d_in[1];
    const float* x2   = (const float*)d_in[2];
    const float* yolo = (const float*)d_in[3];
    const int*   ridx = (const int*)d_in[4];
    const float* nw0 = (const float*)d_in[5];
    const float* nb0 = (const float*)d_in[6];
    const float* nw1 = (const float*)d_in[7];
    const float* nb1 = (const float*)d_in[8];
    const float* nw2 = (const float*)d_in[9];
    const float* nb2 = (const float*)d_in[10];
    const float* cw1[3] = {(const float*)d_in[11], (const float*)d_in[16], (const float*)d_in[21]};
    const float* cb1[3] = {(const float*)d_in[12], (const float*)d_in[17], (const float*)d_in[22]};
    const float* cw2[3] = {(const float*)d_in[13], (const float*)d_in[18], (const float*)d_in[23]};
    const float* cb2[3] = {(const float*)d_in[14], (const float*)d_in[19], (const float*)d_in[24]};
    const float* csw[3] = {(const float*)d_in[15], (const float*)d_in[20], (const float*)d_in[25]};

    float* out = (float*)d_out;
    const int yolo_n = NB * 8400 * 6;
    const int emb_n  = NB * KIDX * C_EMB;
    float* emb_out = out;
    if (out_size >= yolo_n + emb_n) {
        cudaMemcpyAsync(out, yolo, (size_t)in_sizes[3] * sizeof(float),
                        cudaMemcpyDeviceToDevice, 0);
        emb_out = out + yolo_n;
    }

    float *y0p, *y1p, *y2p;
    cudaGetSymbolAddress((void**)&y0p, g_y0s0);
    cudaGetSymbolAddress((void**)&y1p, g_y0s1);
    cudaGetSymbolAddress((void**)&y2p, g_y0s2);
    __nv_bfloat16 *wh0, *wl0, *wh1, *wl1, *wh2, *wl2;
    cudaGetSymbolAddress((void**)&wh0, g_wh0);
    cudaGetSymbolAddress((void**)&wl0, g_wl0);
    cudaGetSymbolAddress((void**)&wh1, g_wh1);
    cudaGetSymbolAddress((void**)&wl1, g_wl1);
    cudaGetSymbolAddress((void**)&wh2, g_wh2);
    cudaGetSymbolAddress((void**)&wl2, g_wl2);
    float *smx0p, *sav0p, *s0p, *smx1p, *sav1p, *s1p, *smx2p, *sav2p, *s2p;
    cudaGetSymbolAddress((void**)&smx0p, g_smx0);
    cudaGetSymbolAddress((void**)&sav0p, g_sav0);
    cudaGetSymbolAddress((void**)&s0p,   g_s0);
    cudaGetSymbolAddress((void**)&smx1p, g_smx1);
    cudaGetSymbolAddress((void**)&sav1p, g_sav1);
    cudaGetSymbolAddress((void**)&s1p,   g_s1);
    cudaGetSymbolAddress((void**)&smx2p, g_smx2);
    cudaGetSymbolAddress((void**)&sav2p, g_sav2);
    cudaGetSymbolAddress((void**)&s2p,   g_s2);

    cudaFuncSetAttribute((const void*)tc_gemm<256>,
                         cudaFuncAttributeMaxDynamicSharedMemorySize, SMEM_GEMM);
    cudaFuncSetAttribute((const void*)tc_gemm<512>,
                         cudaFuncAttributeMaxDynamicSharedMemorySize, SMEM_GEMM);
    cudaFuncSetAttribute((const void*)tc_gemm<1024>,
                         cudaFuncAttributeMaxDynamicSharedMemorySize, SMEM_GEMM);

    init_stats<<<(3 * NB * C_EMB + 255) / 256, 256>>>();

    convert_w<<<(C_EMB * 256  + 255) / 256, 256>>>(nw0, wh0, wl0, C_EMB * 256);
    convert_w<<<(C_EMB * 512  + 255) / 256, 256>>>(nw1, wh1, wl1, C_EMB * 512);
    convert_w<<<(C_EMB * 1024 + 255) / 256, 256>>>(nw2, wh2, wl2, C_EMB * 1024);

    tc_gemm<256><<<dim3(HW_0 / 128, NB), 256, SMEM_GEMM>>>(x0, wh0, wl0, nb0, y0p, HW_0, 0);
    tc_gemm<512><<<dim3((HW_1 + 127) / 128, NB), 256, SMEM_GEMM>>>(x1, wh1, wl1, nb1, y1p, HW_1, 1);
    tc_gemm<1024><<<dim3((HW_2 + 127) / 128, NB), 256, SMEM_GEMM>>>(x2, wh2, wl2, nb2, y2p, HW_2, 2);

    gate_kernel<<<NB, 128>>>(cw1[0], cb1[0], cw2[0], cb2[0], 0, HW_0);
    gate_kernel<<<NB, 128>>>(cw1[1], cb1[1], cw2[1], cb2[1], 1, HW_1);
    gate_kernel<<<NB, 128>>>(cw1[2], cb1[2], cw2[2], cb2[2], 2, HW_2);

    sam_stats<<<NB * HW_0 / 8, 256>>>(y0p, smx0p, sav0p, HW_0, 0);
    sam_stats<<<NB * HW_1 / 8, 256>>>(y1p, smx1p, sav1p, HW_1, 1);
    sam_stats<<<NB * HW_2 / 8, 256>>>(y2p, smx2p, sav2p, HW_2, 2);

    conv7<<<(NB * HW_0 + 255) / 256, 256>>>(smx0p, sav0p, csw[0], s0p, SIDE0);
    conv7<<<(NB * HW_1 + 255) / 256, 256>>>(smx1p, sav1p, csw[1], s1p, SIDE1);
    conv7<<<(NB * HW_2 + 255) / 256, 256>>>(smx2p, sav2p, csw[2], s2p, SIDE2);

    gather_out<<<NB * KIDX, 128>>>(ridx, emb_out);
}

// round 4
// speedup vs baseline: 2.5744x; 1.5979x over previous
#include <cuda_runtime.h>
#include <cuda_fp16.h>
#include <cstdint>
#include <math.h>

// ---------------- problem constants ----------------
#define NB 32
#define C_EMB 128
#define HID 32
#define KIDX 100

#define HW_0 6400
#define HW_1 1600
#define HW_2 400
#define SIDE0 80
#define SIDE1 40
#define SIDE2 20

#define WSCALE 64.0f
#define WSCALE_INV (1.0f / 64.0f)

// ---------------- device scratch ----------------
__device__ __align__(128) float g_y0s0[(size_t)NB * HW_0 * C_EMB];
__device__ __align__(128) float g_y0s1[(size_t)NB * HW_1 * C_EMB];
__device__ __align__(128) float g_y0s2[(size_t)NB * HW_2 * C_EMB];

// converted weights (scaled by 64): [m][k] fp16 hi/lo
__device__ __align__(128) __half g_wh0[C_EMB * 256],  g_wl0[C_EMB * 256];
__device__ __align__(128) __half g_wh1[C_EMB * 512],  g_wl1[C_EMB * 512];
__device__ __align__(128) __half g_wh2[C_EMB * 1024], g_wl2[C_EMB * 1024];

__device__ unsigned g_maxenc[3 * NB * C_EMB];
__device__ float    g_sum[3 * NB * C_EMB];
__device__ float    g_gate[3 * NB * C_EMB];

__device__ float g_smx0[NB * HW_0], g_sav0[NB * HW_0], g_s0[NB * HW_0];
__device__ float g_smx1[NB * HW_1], g_sav1[NB * HW_1], g_s1[NB * HW_1];
__device__ float g_smx2[NB * HW_2], g_sav2[NB * HW_2], g_s2[NB * HW_2];

// ---------------- helpers ----------------
__device__ __forceinline__ uint32_t smem_to_u32(const void* p) {
    uint32_t a;
    asm("{ .reg .u64 t; cvta.to.shared.u64 t, %1; cvt.u32.u64 %0, t; }" : "=r"(a) : "l"(p));
    return a;
}
__device__ __forceinline__ void ldsm_x4(uint32_t* r, uint32_t addr) {
    asm volatile("ldmatrix.sync.aligned.m8n8.x4.shared.b16 {%0,%1,%2,%3}, [%4];"
                 : "=r"(r[0]), "=r"(r[1]), "=r"(r[2]), "=r"(r[3]) : "r"(addr));
}
__device__ __forceinline__ void ldsm_x4_t(uint32_t* r, uint32_t addr) {
    asm volatile("ldmatrix.sync.aligned.m8n8.x4.trans.shared.b16 {%0,%1,%2,%3}, [%4];"
                 : "=r"(r[0]), "=r"(r[1]), "=r"(r[2]), "=r"(r[3]) : "r"(addr));
}
__device__ __forceinline__ void mma_f16(float* d, const uint32_t* a, const uint32_t* b) {
    asm volatile("mma.sync.aligned.m16n8k16.row.col.f32.f16.f16.f32 "
                 "{%0,%1,%2,%3}, {%4,%5,%6,%7}, {%8,%9}, {%0,%1,%2,%3};"
                 : "+f"(d[0]), "+f"(d[1]), "+f"(d[2]), "+f"(d[3])
                 : "r"(a[0]), "r"(a[1]), "r"(a[2]), "r"(a[3]), "r"(b[0]), "r"(b[1]));
}
__device__ __forceinline__ void cp_async16(uint32_t saddr, const void* gptr) {
    asm volatile("cp.async.cg.shared.global [%0], [%1], 16;" :: "r"(saddr), "l"(gptr));
}
#define CP_COMMIT() asm volatile("cp.async.commit_group;" ::: "memory")
#define CP_WAIT0()  asm volatile("cp.async.wait_group 0;"  ::: "memory")

__device__ __forceinline__ unsigned encf(float f) {
    unsigned u = __float_as_uint(f);
    return (u & 0x80000000u) ? ~u : (u | 0x80000000u);
}
__device__ __forceinline__ float decf(unsigned e) {
    return (e & 0x80000000u) ? __uint_as_float(e & 0x7FFFFFFFu) : __uint_as_float(~e);
}
__device__ __forceinline__ float sigmoidf_(float x) { return 1.0f / (1.0f + __expf(-x)); }

// ---------------- init stats ----------------
__global__ void init_stats() {
    int i = blockIdx.x * blockDim.x + threadIdx.x;
    if (i < 3 * NB * C_EMB) { g_maxenc[i] = 0u; g_sum[i] = 0.0f; }
}

// ---------------- weight conversion: fp32 -> fp16 hi/lo, scaled x64 ----------------
__global__ void convert_w(const float* __restrict__ W, __half* __restrict__ Wh,
                          __half* __restrict__ Wl, int n) {
    int i = blockIdx.x * 256 + threadIdx.x;
    if (i >= n) return;
    float v = W[i] * WSCALE;
    __half h = __float2half_rn(v);
    __half l = __float2half_rn(v - __half2float(h));
    Wh[i] = h; Wl[i] = l;
}

// ---------------- merged HMMA GEMM, fp16 2-term split, pipelined ----------------
// Y[b][hw][m] = (1/64) * sum_k W64[m][k] * X[b][k][hw] + bias[m]
// CTA tile: 128 hw (M) x 128 ch (N); K-chunk 64; double-buffered smem.
// smem layout:
//   X fp16 tiles:  2 x 16 KB at 0, 16384
//   W fp16 tiles:  2 x (16 KB hi + 16 KB lo) at 32768, 65536
//   bias at 98304
static constexpr int SM_XB0  = 0;
static constexpr int SM_WB0  = 32768;
static constexpr int SM_BIAS = 98304;
static constexpr int SMEM_GEMM = 98304 + 512;

__global__ void __launch_bounds__(256, 2)
gemm_all(const float* __restrict__ x0, const float* __restrict__ x1, const float* __restrict__ x2,
         const __half* __restrict__ wh0, const __half* __restrict__ wl0,
         const __half* __restrict__ wh1, const __half* __restrict__ wl1,
         const __half* __restrict__ wh2, const __half* __restrict__ wl2,
         const float* __restrict__ nb0, const float* __restrict__ nb1, const float* __restrict__ nb2,
         float* __restrict__ y0, float* __restrict__ y1, float* __restrict__ y2) {
    extern __shared__ __align__(128) char smem[];
    const uint32_t sb = smem_to_u32(smem);
    const int tid  = threadIdx.x;
    const int lane = tid & 31;
    const int wid  = tid >> 5;
    const int wm   = wid & 3;
    const int wn   = wid >> 2;
    const int b    = blockIdx.y;

    // ---- scale select ----
    const float* X; const __half* Wh; const __half* Wl; const float* bias; float* Y;
    int CIN, HW, scale, tile;
    int bx = blockIdx.x;
    if (bx < 50)      { tile = bx;      X = x0; Wh = wh0; Wl = wl0; bias = nb0; Y = y0; CIN = 256;  HW = HW_0; scale = 0; }
    else if (bx < 63) { tile = bx - 50; X = x1; Wh = wh1; Wl = wl1; bias = nb1; Y = y1; CIN = 512;  HW = HW_1; scale = 1; }
    else              { tile = bx - 63; X = x2; Wh = wh2; Wl = wl2; bias = nb2; Y = y2; CIN = 1024; HW = HW_2; scale = 2; }
    const int hw0 = tile * 128;
    int nvalid = HW - hw0; if (nvalid > 128) nvalid = 128;
    const int nchunk = CIN >> 6;

    if (tid < 32) ((float4*)(smem + SM_BIAS))[tid] = ((const float4*)bias)[tid];

    // ldmatrix address components
    const int ti = lane & 7;
    const int gq = lane >> 3;
    const int aKrow = ((gq >> 1) << 3) + ti;
    const int aMsel = (gq & 1) << 3;
    const int bKsel = gq & 1;
    const int bNrow = ((gq >> 1) << 3) + ti;

    uint32_t offA[2];
#pragma unroll
    for (int mt = 0; mt < 2; mt++) {
        int m0 = wm * 32 + mt * 16 + aMsel;
        offA[mt] = (uint32_t)(aKrow * 256 + ((((m0 >> 3) ^ (aKrow & 7)) << 4)));
    }

    float acc[2][8][4];
#pragma unroll
    for (int mt = 0; mt < 2; mt++)
#pragma unroll
        for (int nt = 0; nt < 8; nt++)
#pragma unroll
            for (int r = 0; r < 4; r++) acc[mt][nt][r] = 0.0f;

    // X load mapping
    const int xr  = tid >> 2;
    const int xc0 = tid & 3;
    const float* xbase = X + ((size_t)b * CIN) * HW + hw0;

    // W cp.async mapping: 4 lines per tile per thread
    const int wn_r  = (tid * 4) >> 3;        // wait, compute per-line below

    float4 xr4[8];

    // ---- lambda-ish helpers via macros ----
#define LDG_X(K0) do { \
        const float* row_ = xbase + (size_t)((K0) + xr) * HW; \
        _Pragma("unroll") \
        for (int i_ = 0; i_ < 8; i_++) { \
            int c4_ = xc0 + 4 * i_; \
            int hwb_ = c4_ * 4; \
            xr4[i_] = (hw0 + hwb_ < HW) ? *(const float4*)(row_ + hwb_) \
                                        : make_float4(0.f, 0.f, 0.f, 0.f); \
        } \
    } while (0)

#define STS_X(BUF) do { \
        uint32_t base_ = sb + SM_XB0 + (BUF) * 16384; \
        _Pragma("unroll") \
        for (int i_ = 0; i_ < 8; i_++) { \
            int c4_ = xc0 + 4 * i_; \
            __half2 p0_ = __floats2half2_rn(xr4[i_].x, xr4[i_].y); \
            __half2 p1_ = __floats2half2_rn(xr4[i_].z, xr4[i_].w); \
            uint32_t u0_ = *(uint32_t*)&p0_, u1_ = *(uint32_t*)&p1_; \
            uint32_t off_ = (uint32_t)(xr * 256 + ((((c4_ >> 1) ^ (xr & 7)) << 4)) + (c4_ & 1) * 8); \
            asm volatile("st.shared.v2.b32 [%0], {%1, %2};" :: "r"(base_ + off_), "r"(u0_), "r"(u1_)); \
        } \
    } while (0)

#define CPA_W(K0, BUF) do { \
        uint32_t wb_ = sb + SM_WB0 + (BUF) * 32768; \
        _Pragma("unroll") \
        for (int i_ = 0; i_ < 4; i_++) { \
            int idx_ = tid + i_ * 256; \
            int n_   = idx_ >> 3; \
            int seg_ = idx_ & 7; \
            uint32_t off_ = (uint32_t)(n_ * 128 + ((seg_ ^ (n_ & 7)) << 4)); \
            cp_async16(wb_ + off_,         Wh + (size_t)n_ * CIN + (K0) + seg_ * 8); \
            cp_async16(wb_ + 16384 + off_, Wl + (size_t)n_ * CIN + (K0) + seg_ * 8); \
        } \
    } while (0)

    // ---- prologue: chunk 0 ----
    CPA_W(0, 0);
    CP_COMMIT();
    LDG_X(0);
    STS_X(0);
    CP_WAIT0();
    __syncthreads();

    for (int ck = 0; ; ck++) {
        const int cur = ck & 1;
        const bool more = (ck + 1 < nchunk);
        if (more) {
            CPA_W((ck + 1) * 64, cur ^ 1);
            CP_COMMIT();
            LDG_X((ck + 1) * 64);
        }
        // ---- MMAs on current buffers ----
        const uint32_t xb = sb + SM_XB0 + cur * 16384;
        const uint32_t wb = sb + SM_WB0 + cur * 32768;
#pragma unroll
        for (int ks = 0; ks < 4; ks++) {
            const uint32_t kb256 = (uint32_t)(ks * 16 * 256);
            uint32_t ah[2][4];
            ldsm_x4_t(ah[0], xb + kb256 + offA[0]);
            ldsm_x4_t(ah[1], xb + kb256 + offA[1]);
#pragma unroll
            for (int np = 0; np < 4; np++) {
                int nrow = wn * 64 + np * 16 + bNrow;
                int kseg = ks * 2 + bKsel;
                uint32_t boff = (uint32_t)(nrow * 128 + (((kseg ^ (nrow & 7)) << 4)));
                uint32_t bh[4], bl[4];
                ldsm_x4(bh, wb + boff);
                ldsm_x4(bl, wb + 16384 + boff);
#pragma unroll
                for (int mt = 0; mt < 2; mt++)
#pragma unroll
                    for (int s = 0; s < 2; s++)
                        mma_f16(acc[mt][np * 2 + s], ah[mt], &bh[s * 2]);
#pragma unroll
                for (int mt = 0; mt < 2; mt++)
#pragma unroll
                    for (int s = 0; s < 2; s++)
                        mma_f16(acc[mt][np * 2 + s], ah[mt], &bl[s * 2]);
            }
        }
        if (!more) break;
        STS_X(cur ^ 1);
        CP_WAIT0();
        __syncthreads();
    }
    __syncthreads();

    // ---- stage C through smem: Cs[128 hw][128 ch] fp32 (reuses tile buffers) ----
    float* Cs = (float*)smem;
#pragma unroll
    for (int mt = 0; mt < 2; mt++) {
#pragma unroll
        for (int nt = 0; nt < 8; nt++) {
            int r0 = wm * 32 + mt * 16 + (lane >> 2);
            int c0 = wn * 64 + nt * 8 + (lane & 3) * 2;
            *(float2*)&Cs[r0 * 128 + c0]       = make_float2(acc[mt][nt][0], acc[mt][nt][1]);
            *(float2*)&Cs[(r0 + 8) * 128 + c0] = make_float2(acc[mt][nt][2], acc[mt][nt][3]);
        }
    }
    __syncthreads();

    const float* bsm = (const float*)(smem + SM_BIAS);
    float* yb = Y + ((size_t)b * HW + hw0) * C_EMB;
    for (int idx = tid; idx < nvalid * 32; idx += 256) {
        int r  = idx >> 5;
        int c4 = idx & 31;
        float4 v = ((const float4*)(Cs + r * 128))[c4];
        float4 bv = ((const float4*)bsm)[c4];
        v.x = v.x * WSCALE_INV + bv.x;
        v.y = v.y * WSCALE_INV + bv.y;
        v.z = v.z * WSCALE_INV + bv.z;
        v.w = v.w * WSCALE_INV + bv.w;
        ((float4*)(yb + (size_t)r * C_EMB))[c4] = v;
    }
    if (tid < 128) {
        float bv = bsm[tid];
        float mx = -3.4e38f, sm = 0.0f;
        for (int r = 0; r < nvalid; r++) {
            float v = Cs[r * 128 + tid] * WSCALE_INV + bv;
            mx = fmaxf(mx, v);
            sm += v;
        }
        int o = (scale * NB + b) * C_EMB + tid;
        atomicMax(&g_maxenc[o], encf(mx));
        atomicAdd(&g_sum[o], sm);
    }
}

// ---------------- gate: tiny shared MLP + sigmoid ----------------
__global__ void gate_kernel(const float* __restrict__ w1, const float* __restrict__ b1,
                            const float* __restrict__ w2, const float* __restrict__ b2,
                            int scale, int HW) {
    __shared__ float vmx[C_EMB], vav[C_EMB], hmx[HID], hav[HID];
    const int b = blockIdx.x;
    const int c = threadIdx.x;
    const int o = (scale * NB + b) * C_EMB + c;
    vmx[c] = decf(g_maxenc[o]);
    vav[c] = g_sum[o] * (1.0f / (float)HW);
    __syncthreads();
    if (c < HID) {
        float s1 = b1[c], s2 = b1[c];
        for (int k = 0; k < C_EMB; k++) {
            float w = w1[c * C_EMB + k];
            s1 += w * vmx[k];
            s2 += w * vav[k];
        }
        hmx[c] = fmaxf(s1, 0.0f);
        hav[c] = fmaxf(s2, 0.0f);
    }
    __syncthreads();
    float o1 = b2[c], o2 = b2[c];
    for (int k = 0; k < HID; k++) {
        float w = w2[c * HID + k];
        o1 += w * hmx[k];
        o2 += w * hav[k];
    }
    g_gate[o] = sigmoidf_(o1 + o2);
}

// ---------------- SAM stats ----------------
__global__ void sam_stats(const float* __restrict__ Y, float* __restrict__ smx,
                          float* __restrict__ sav, int HW, int scale) {
    __shared__ float gsh[C_EMB];
    const int tid  = threadIdx.x;
    const int gw   = (blockIdx.x * 256 + tid) >> 5;
    const int lane = tid & 31;
    const int b    = gw / HW;
    const int hw   = gw - b * HW;
    if (tid < C_EMB) gsh[tid] = g_gate[(scale * NB + b) * C_EMB + tid];
    __syncthreads();
    float4 v = *(const float4*)&Y[((size_t)b * HW + hw) * C_EMB + lane * 4];
    float4 g = *(const float4*)&gsh[lane * 4];
    float a0 = v.x * g.x, a1 = v.y * g.y, a2 = v.z * g.z, a3 = v.w * g.w;
    float mx = fmaxf(fmaxf(a0, a1), fmaxf(a2, a3));
    float sm = a0 + a1 + a2 + a3;
#pragma unroll
    for (int o = 16; o; o >>= 1) {
        mx = fmaxf(mx, __shfl_xor_sync(0xFFFFFFFFu, mx, o));
        sm += __shfl_xor_sync(0xFFFFFFFFu, sm, o);
    }
    if (lane == 0) {
        smx[gw] = mx;
        sav[gw] = sm * (1.0f / (float)C_EMB);
    }
}

// ---------------- 7x7 conv on [max, mean] ----------------
__global__ void conv7(const float* __restrict__ smx, const float* __restrict__ sav,
                      const float* __restrict__ sw, float* __restrict__ S, int SIDE) {
    __shared__ float w[98];
    const int tid = threadIdx.x;
    if (tid < 98) w[tid] = sw[tid];
    __syncthreads();
    const int HW = SIDE * SIDE;
    const int p  = blockIdx.x * 256 + tid;
    if (p >= NB * HW) return;
    const int b  = p / HW, hw = p - b * HW;
    const int y  = hw / SIDE, x = hw - y * SIDE;
    const float* mp = smx + (size_t)b * HW;
    const float* ap = sav + (size_t)b * HW;
    float acc = 0.0f;
#pragma unroll
    for (int dy = -3; dy <= 3; dy++) {
        int yy = y + dy;
        if (yy < 0 || yy >= SIDE) continue;
#pragma unroll
        for (int dx = -3; dx <= 3; dx++) {
            int xx = x + dx;
            if (xx < 0 || xx >= SIDE) continue;
            int wi = (dy + 3) * 7 + (dx + 3);
            int q  = yy * SIDE + xx;
            acc += mp[q] * w[wi] + ap[q] * w[49 + wi];
        }
    }
    S[p] = acc;
}

// ---------------- gather ----------------
__global__ void gather_out(const int* __restrict__ idx, float* __restrict__ out) {
    const int row = blockIdx.x;
    const int c   = threadIdx.x;
    const int b   = row / KIDX;
    const int id  = idx[row];
    const float* Y; const float* S; int HW, scale, p;
    if (id < HW_0)              { Y = g_y0s0; S = g_s0; HW = HW_0; scale = 0; p = id; }
    else if (id < HW_0 + HW_1)  { Y = g_y0s1; S = g_s1; HW = HW_1; scale = 1; p = id - HW_0; }
    else                        { Y = g_y0s2; S = g_s2; HW = HW_2; scale = 2; p = id - (HW_0 + HW_1); }
    float y   = Y[((size_t)b * HW + p) * C_EMB + c];
    float g   = g_gate[(scale * NB + b) * C_EMB + c];
    float sig = sigmoidf_(S[b * HW + p]);
    out[(size_t)row * C_EMB + c] = y * (1.0f + g * sig);
}

// ---------------- launch ----------------
extern "C" void kernel_launch(void* const* d_in, const int* in_sizes, int n_in,
                              void* d_out, int out_size) {
    const float* x0   = (const float*)d_in[0];
    const float* x1   = (const float*)d_in[1];
    const float* x2   = (const float*)d_in[2];
    const float* yolo = (const float*)d_in[3];
    const int*   ridx = (const int*)d_in[4];
    const float* nw0 = (const float*)d_in[5];
    const float* nb0 = (const float*)d_in[6];
    const float* nw1 = (const float*)d_in[7];
    const float* nb1 = (const float*)d_in[8];
    const float* nw2 = (const float*)d_in[9];
    const float* nb2 = (const float*)d_in[10];
    const float* cw1[3] = {(const float*)d_in[11], (const float*)d_in[16], (const float*)d_in[21]};
    const float* cb1[3] = {(const float*)d_in[12], (const float*)d_in[17], (const float*)d_in[22]};
    const float* cw2[3] = {(const float*)d_in[13], (const float*)d_in[18], (const float*)d_in[23]};
    const float* cb2[3] = {(const float*)d_in[14], (const float*)d_in[19], (const float*)d_in[24]};
    const float* csw[3] = {(const float*)d_in[15], (const float*)d_in[20], (const float*)d_in[25]};

    float* out = (float*)d_out;
    const int yolo_n = NB * 8400 * 6;
    const int emb_n  = NB * KIDX * C_EMB;
    float* emb_out = out;
    if (out_size >= yolo_n + emb_n) {
        cudaMemcpyAsync(out, yolo, (size_t)in_sizes[3] * sizeof(float),
                        cudaMemcpyDeviceToDevice, 0);
        emb_out = out + yolo_n;
    }

    float *y0p, *y1p, *y2p;
    cudaGetSymbolAddress((void**)&y0p, g_y0s0);
    cudaGetSymbolAddress((void**)&y1p, g_y0s1);
    cudaGetSymbolAddress((void**)&y2p, g_y0s2);
    __half *wh0, *wl0, *wh1, *wl1, *wh2, *wl2;
    cudaGetSymbolAddress((void**)&wh0, g_wh0);
    cudaGetSymbolAddress((void**)&wl0, g_wl0);
    cudaGetSymbolAddress((void**)&wh1, g_wh1);
    cudaGetSymbolAddress((void**)&wl1, g_wl1);
    cudaGetSymbolAddress((void**)&wh2, g_wh2);
    cudaGetSymbolAddress((void**)&wl2, g_wl2);
    float *smx0p, *sav0p, *s0p, *smx1p, *sav1p, *s1p, *smx2p, *sav2p, *s2p;
    cudaGetSymbolAddress((void**)&smx0p, g_smx0);
    cudaGetSymbolAddress((void**)&sav0p, g_sav0);
    cudaGetSymbolAddress((void**)&s0p,   g_s0);
    cudaGetSymbolAddress((void**)&smx1p, g_smx1);
    cudaGetSymbolAddress((void**)&sav1p, g_sav1);
    cudaGetSymbolAddress((void**)&s1p,   g_s1);
    cudaGetSymbolAddress((void**)&smx2p, g_smx2);
    cudaGetSymbolAddress((void**)&sav2p, g_sav2);
    cudaGetSymbolAddress((void**)&s2p,   g_s2);

    cudaFuncSetAttribute((const void*)gemm_all,
                         cudaFuncAttributeMaxDynamicSharedMemorySize, SMEM_GEMM);

    init_stats<<<(3 * NB * C_EMB + 255) / 256, 256>>>();

    convert_w<<<(C_EMB * 256  + 255) / 256, 256>>>(nw0, wh0, wl0, C_EMB * 256);
    convert_w<<<(C_EMB * 512  + 255) / 256, 256>>>(nw1, wh1, wl1, C_EMB * 512);
    convert_w<<<(C_EMB * 1024 + 255) / 256, 256>>>(nw2, wh2, wl2, C_EMB * 1024);

    gemm_all<<<dim3(67, NB), 256, SMEM_GEMM>>>(
        x0, x1, x2, wh0, wl0, wh1, wl1, wh2, wl2, nb0, nb1, nb2, y0p, y1p, y2p);

    gate_kernel<<<NB, 128>>>(cw1[0], cb1[0], cw2[0], cb2[0], 0, HW_0);
    gate_kernel<<<NB, 128>>>(cw1[1], cb1[1], cw2[1], cb2[1], 1, HW_1);
    gate_kernel<<<NB, 128>>>(cw1[2], cb1[2], cw2[2], cb2[2], 2, HW_2);

    sam_stats<<<NB * HW_0 / 8, 256>>>(y0p, smx0p, sav0p, HW_0, 0);
    sam_stats<<<NB * HW_1 / 8, 256>>>(y1p, smx1p, sav1p, HW_1, 1);
    sam_stats<<<NB * HW_2 / 8, 256>>>(y2p, smx2p, sav2p, HW_2, 2);

    conv7<<<(NB * HW_0 + 255) / 256, 256>>>(smx0p, sav0p, csw[0], s0p, SIDE0);
    conv7<<<(NB * HW_1 + 255) / 256, 256>>>(smx1p, sav1p, csw[1], s1p, SIDE1);
    conv7<<<(NB * HW_2 + 255) / 256, 256>>>(smx2p, sav2p, csw[2], s2p, SIDE2);

    gather_out<<<NB * KIDX, 128>>>(ridx, emb_out);
}

// round 5
// speedup vs baseline: 3.0287x; 1.1765x over previous
#include <cuda_runtime.h>
#include <cuda_fp16.h>
#include <cstdint>
#include <math.h>

// ---------------- problem constants ----------------
#define NB 32
#define C_EMB 128
#define HID 32
#define KIDX 100

#define HW_0 6400
#define HW_1 1600
#define HW_2 400
#define SIDE0 80
#define SIDE1 40
#define SIDE2 20

// ---------------- device scratch ----------------
__device__ __align__(128) float g_y0s0[(size_t)NB * HW_0 * C_EMB];
__device__ __align__(128) float g_y0s1[(size_t)NB * HW_1 * C_EMB];
__device__ __align__(128) float g_y0s2[(size_t)NB * HW_2 * C_EMB];

// converted weights: [m][k] fp16
__device__ __align__(128) __half g_wh0[C_EMB * 256];
__device__ __align__(128) __half g_wh1[C_EMB * 512];
__device__ __align__(128) __half g_wh2[C_EMB * 1024];

__device__ unsigned g_maxenc[3 * NB * C_EMB];
__device__ float    g_sum[3 * NB * C_EMB];
__device__ float    g_gate[3 * NB * C_EMB];

__device__ float g_smx0[NB * HW_0], g_sav0[NB * HW_0], g_s0[NB * HW_0];
__device__ float g_smx1[NB * HW_1], g_sav1[NB * HW_1], g_s1[NB * HW_1];
__device__ float g_smx2[NB * HW_2], g_sav2[NB * HW_2], g_s2[NB * HW_2];

// ---------------- helpers ----------------
__device__ __forceinline__ uint32_t smem_to_u32(const void* p) {
    uint32_t a;
    asm("{ .reg .u64 t; cvta.to.shared.u64 t, %1; cvt.u32.u64 %0, t; }" : "=r"(a) : "l"(p));
    return a;
}
__device__ __forceinline__ void ldsm_x4(uint32_t* r, uint32_t addr) {
    asm volatile("ldmatrix.sync.aligned.m8n8.x4.shared.b16 {%0,%1,%2,%3}, [%4];"
                 : "=r"(r[0]), "=r"(r[1]), "=r"(r[2]), "=r"(r[3]) : "r"(addr));
}
__device__ __forceinline__ void ldsm_x4_t(uint32_t* r, uint32_t addr) {
    asm volatile("ldmatrix.sync.aligned.m8n8.x4.trans.shared.b16 {%0,%1,%2,%3}, [%4];"
                 : "=r"(r[0]), "=r"(r[1]), "=r"(r[2]), "=r"(r[3]) : "r"(addr));
}
__device__ __forceinline__ void mma_f16(float* d, const uint32_t* a, const uint32_t* b) {
    asm volatile("mma.sync.aligned.m16n8k16.row.col.f32.f16.f16.f32 "
                 "{%0,%1,%2,%3}, {%4,%5,%6,%7}, {%8,%9}, {%0,%1,%2,%3};"
                 : "+f"(d[0]), "+f"(d[1]), "+f"(d[2]), "+f"(d[3])
                 : "r"(a[0]), "r"(a[1]), "r"(a[2]), "r"(a[3]), "r"(b[0]), "r"(b[1]));
}
__device__ __forceinline__ void cp_async16(uint32_t saddr, const void* gptr) {
    asm volatile("cp.async.cg.shared.global [%0], [%1], 16;" :: "r"(saddr), "l"(gptr));
}
#define CP_COMMIT() asm volatile("cp.async.commit_group;" ::: "memory")
#define CP_WAIT0()  asm volatile("cp.async.wait_group 0;"  ::: "memory")

__device__ __forceinline__ unsigned encf(float f) {
    unsigned u = __float_as_uint(f);
    return (u & 0x80000000u) ? ~u : (u | 0x80000000u);
}
__device__ __forceinline__ float decf(unsigned e) {
    return (e & 0x80000000u) ? __uint_as_float(e & 0x7FFFFFFFu) : __uint_as_float(~e);
}
__device__ __forceinline__ float sigmoidf_(float x) { return 1.0f / (1.0f + __expf(-x)); }

// ---------------- init stats ----------------
__global__ void init_stats() {
    int i = blockIdx.x * blockDim.x + threadIdx.x;
    if (i < 3 * NB * C_EMB) { g_maxenc[i] = 0u; g_sum[i] = 0.0f; }
}

// ---------------- weight conversion: fp32 -> fp16 ----------------
__global__ void convert_w(const float* __restrict__ W, __half* __restrict__ Wh, int n) {
    int i = blockIdx.x * 256 + threadIdx.x;
    if (i < n) Wh[i] = __float2half_rn(W[i]);
}
__global__ void convert_w2(const float* __restrict__ W1, __half* __restrict__ Wh1, int n1,
                           const float* __restrict__ W2, __half* __restrict__ Wh2, int n2) {
    int i = blockIdx.x * 256 + threadIdx.x;
    if (i < n1) Wh1[i] = __float2half_rn(W1[i]);
    else if (i < n1 + n2) Wh2[i - n1] = __float2half_rn(W2[i - n1]);
}

// ---------------- merged HMMA GEMM, single fp16 term, pipelined ----------------
// Y[b][hw][m] = sum_k W[m][k] * X[b][k][hw] + bias[m]
// CTA tile: 128 hw (M) x 128 ch (N); K-chunk 64; double-buffered smem.
// smem: X fp16 2x16KB at 0; W fp16 2x16KB at 32768; bias at 65536.
static constexpr int SM_XB0  = 0;
static constexpr int SM_WB0  = 32768;
static constexpr int SM_BIAS = 65536;
static constexpr int SMEM_GEMM = 65536 + 512;

__global__ void __launch_bounds__(256, 2)
gemm_all(const float* __restrict__ x0, const float* __restrict__ x1, const float* __restrict__ x2,
         const __half* __restrict__ wh0, const __half* __restrict__ wh1, const __half* __restrict__ wh2,
         const float* __restrict__ nb0, const float* __restrict__ nb1, const float* __restrict__ nb2,
         float* __restrict__ y0, float* __restrict__ y1, float* __restrict__ y2) {
    extern __shared__ __align__(128) char smem[];
    const uint32_t sb = smem_to_u32(smem);
    const int tid  = threadIdx.x;
    const int lane = tid & 31;
    const int wid  = tid >> 5;
    const int wm   = wid & 3;
    const int wn   = wid >> 2;
    const int b    = blockIdx.y;

    // ---- scale select ----
    const float* X; const __half* Wh; const float* bias; float* Y;
    int CIN, HW, scale, tile;
    int bx = blockIdx.x;
    if (bx < 50)      { tile = bx;      X = x0; Wh = wh0; bias = nb0; Y = y0; CIN = 256;  HW = HW_0; scale = 0; }
    else if (bx < 63) { tile = bx - 50; X = x1; Wh = wh1; bias = nb1; Y = y1; CIN = 512;  HW = HW_1; scale = 1; }
    else              { tile = bx - 63; X = x2; Wh = wh2; bias = nb2; Y = y2; CIN = 1024; HW = HW_2; scale = 2; }
    const int hw0 = tile * 128;
    int nvalid = HW - hw0; if (nvalid > 128) nvalid = 128;
    const int nchunk = CIN >> 6;

    if (tid < 32) ((float4*)(smem + SM_BIAS))[tid] = ((const float4*)bias)[tid];

    // ldmatrix address components
    const int ti = lane & 7;
    const int gq = lane >> 3;
    const int aKrow = ((gq >> 1) << 3) + ti;
    const int aMsel = (gq & 1) << 3;
    const int bKsel = gq & 1;
    const int bNrow = ((gq >> 1) << 3) + ti;

    uint32_t offA[2];
#pragma unroll
    for (int mt = 0; mt < 2; mt++) {
        int m0 = wm * 32 + mt * 16 + aMsel;
        offA[mt] = (uint32_t)(aKrow * 256 + ((((m0 >> 3) ^ (aKrow & 7)) << 4)));
    }

    float acc[2][8][4];
#pragma unroll
    for (int mt = 0; mt < 2; mt++)
#pragma unroll
        for (int nt = 0; nt < 8; nt++)
#pragma unroll
            for (int r = 0; r < 4; r++) acc[mt][nt][r] = 0.0f;

    // X load mapping: thread -> k-row (0..63), 8 16B-segments
    const int xr  = tid >> 2;
    const int xc0 = tid & 3;
    const float* xbase = X + ((size_t)b * CIN) * HW + hw0;

    uint2 xph[8];   // prefetched X, already fp16-packed

#define LDG_X(K0) do { \
        const float* row_ = xbase + (size_t)((K0) + xr) * HW; \
        _Pragma("unroll") \
        for (int i_ = 0; i_ < 8; i_++) { \
            int c4_ = xc0 + 4 * i_; \
            int hwb_ = c4_ * 4; \
            float4 v_ = (hw0 + hwb_ < HW) ? *(const float4*)(row_ + hwb_) \
                                          : make_float4(0.f, 0.f, 0.f, 0.f); \
            __half2 p0_ = __floats2half2_rn(v_.x, v_.y); \
            __half2 p1_ = __floats2half2_rn(v_.z, v_.w); \
            xph[i_] = make_uint2(*(uint32_t*)&p0_, *(uint32_t*)&p1_); \
        } \
    } while (0)

#define STS_X(BUF) do { \
        uint32_t base_ = sb + SM_XB0 + (BUF) * 16384; \
        _Pragma("unroll") \
        for (int i_ = 0; i_ < 8; i_++) { \
            int c4_ = xc0 + 4 * i_; \
            uint32_t off_ = (uint32_t)(xr * 256 + ((((c4_ >> 1) ^ (xr & 7)) << 4)) + (c4_ & 1) * 8); \
            asm volatile("st.shared.v2.b32 [%0], {%1, %2};" :: "r"(base_ + off_), "r"(xph[i_].x), "r"(xph[i_].y)); \
        } \
    } while (0)

#define CPA_W(K0, BUF) do { \
        uint32_t wb_ = sb + SM_WB0 + (BUF) * 16384; \
        _Pragma("unroll") \
        for (int i_ = 0; i_ < 4; i_++) { \
            int idx_ = tid + i_ * 256; \
            int n_   = idx_ >> 3; \
            int seg_ = idx_ & 7; \
            uint32_t off_ = (uint32_t)(n_ * 128 + ((seg_ ^ (n_ & 7)) << 4)); \
            cp_async16(wb_ + off_, Wh + (size_t)n_ * CIN + (K0) + seg_ * 8); \
        } \
    } while (0)

    // ---- prologue: chunk 0 ----
    CPA_W(0, 0);
    CP_COMMIT();
    LDG_X(0);
    STS_X(0);
    CP_WAIT0();
    __syncthreads();

    for (int ck = 0; ; ck++) {
        const int cur = ck & 1;
        const bool more = (ck + 1 < nchunk);
        if (more) {
            CPA_W((ck + 1) * 64, cur ^ 1);
            CP_COMMIT();
            LDG_X((ck + 1) * 64);
        }
        const uint32_t xb = sb + SM_XB0 + cur * 16384;
        const uint32_t wb = sb + SM_WB0 + cur * 16384;
#pragma unroll
        for (int ks = 0; ks < 4; ks++) {
            const uint32_t kb256 = (uint32_t)(ks * 16 * 256);
            uint32_t ah[2][4];
            ldsm_x4_t(ah[0], xb + kb256 + offA[0]);
            ldsm_x4_t(ah[1], xb + kb256 + offA[1]);
#pragma unroll
            for (int np = 0; np < 4; np++) {
                int nrow = wn * 64 + np * 16 + bNrow;
                int kseg = ks * 2 + bKsel;
                uint32_t boff = (uint32_t)(nrow * 128 + (((kseg ^ (nrow & 7)) << 4)));
                uint32_t bh[4];
                ldsm_x4(bh, wb + boff);
#pragma unroll
                for (int mt = 0; mt < 2; mt++)
#pragma unroll
                    for (int s = 0; s < 2; s++)
                        mma_f16(acc[mt][np * 2 + s], ah[mt], &bh[s * 2]);
            }
        }
        if (!more) break;
        STS_X(cur ^ 1);
        CP_WAIT0();
        __syncthreads();
    }
    __syncthreads();

    // ---- stage C through smem: Cs[128 hw][128 ch] fp32 (reuses tile buffers) ----
    float* Cs = (float*)smem;
#pragma unroll
    for (int mt = 0; mt < 2; mt++) {
#pragma unroll
        for (int nt = 0; nt < 8; nt++) {
            int r0 = wm * 32 + mt * 16 + (lane >> 2);
            int c0 = wn * 64 + nt * 8 + (lane & 3) * 2;
            *(float2*)&Cs[r0 * 128 + c0]       = make_float2(acc[mt][nt][0], acc[mt][nt][1]);
            *(float2*)&Cs[(r0 + 8) * 128 + c0] = make_float2(acc[mt][nt][2], acc[mt][nt][3]);
        }
    }
    __syncthreads();

    const float* bsm = (const float*)(smem + SM_BIAS);
    float* yb = Y + ((size_t)b * HW + hw0) * C_EMB;
    for (int idx = tid; idx < nvalid * 32; idx += 256) {
        int r  = idx >> 5;
        int c4 = idx & 31;
        float4 v = ((const float4*)(Cs + r * 128))[c4];
        float4 bv = ((const float4*)bsm)[c4];
        v.x += bv.x; v.y += bv.y; v.z += bv.z; v.w += bv.w;
        ((float4*)(yb + (size_t)r * C_EMB))[c4] = v;
    }
    if (tid < 128) {
        float bv = bsm[tid];
        float mx = -3.4e38f, sm = 0.0f;
        for (int r = 0; r < nvalid; r++) {
            float v = Cs[r * 128 + tid] + bv;
            mx = fmaxf(mx, v);
            sm += v;
        }
        int o = (scale * NB + b) * C_EMB + tid;
        atomicMax(&g_maxenc[o], encf(mx));
        atomicAdd(&g_sum[o], sm);
    }
}

// ---------------- gate: tiny shared MLP + sigmoid ----------------
__global__ void gate_kernel(const float* __restrict__ w1, const float* __restrict__ b1,
                            const float* __restrict__ w2, const float* __restrict__ b2,
                            int scale, int HW) {
    __shared__ float vmx[C_EMB], vav[C_EMB], hmx[HID], hav[HID];
    const int b = blockIdx.x;
    const int c = threadIdx.x;
    const int o = (scale * NB + b) * C_EMB + c;
    vmx[c] = decf(g_maxenc[o]);
    vav[c] = g_sum[o] * (1.0f / (float)HW);
    __syncthreads();
    if (c < HID) {
        float s1 = b1[c], s2 = b1[c];
        for (int k = 0; k < C_EMB; k++) {
            float w = w1[c * C_EMB + k];
            s1 += w * vmx[k];
            s2 += w * vav[k];
        }
        hmx[c] = fmaxf(s1, 0.0f);
        hav[c] = fmaxf(s2, 0.0f);
    }
    __syncthreads();
    float o1 = b2[c], o2 = b2[c];
    for (int k = 0; k < HID; k++) {
        float w = w2[c * HID + k];
        o1 += w * hmx[k];
        o2 += w * hav[k];
    }
    g_gate[o] = sigmoidf_(o1 + o2);
}

// ---------------- SAM stats ----------------
__global__ void sam_stats(const float* __restrict__ Y, float* __restrict__ smx,
                          float* __restrict__ sav, int HW, int scale) {
    __shared__ float gsh[C_EMB];
    const int tid  = threadIdx.x;
    const int gw   = (blockIdx.x * 256 + tid) >> 5;
    const int lane = tid & 31;
    const int b    = gw / HW;
    const int hw   = gw - b * HW;
    if (tid < C_EMB) gsh[tid] = g_gate[(scale * NB + b) * C_EMB + tid];
    __syncthreads();
    float4 v = *(const float4*)&Y[((size_t)b * HW + hw) * C_EMB + lane * 4];
    float4 g = *(const float4*)&gsh[lane * 4];
    float a0 = v.x * g.x, a1 = v.y * g.y, a2 = v.z * g.z, a3 = v.w * g.w;
    float mx = fmaxf(fmaxf(a0, a1), fmaxf(a2, a3));
    float sm = a0 + a1 + a2 + a3;
#pragma unroll
    for (int o = 16; o; o >>= 1) {
        mx = fmaxf(mx, __shfl_xor_sync(0xFFFFFFFFu, mx, o));
        sm += __shfl_xor_sync(0xFFFFFFFFu, sm, o);
    }
    if (lane == 0) {
        smx[gw] = mx;
        sav[gw] = sm * (1.0f / (float)C_EMB);
    }
}

// ---------------- 7x7 conv on [max, mean] ----------------
__global__ void conv7(const float* __restrict__ smx, const float* __restrict__ sav,
                      const float* __restrict__ sw, float* __restrict__ S, int SIDE) {
    __shared__ float w[98];
    const int tid = threadIdx.x;
    if (tid < 98) w[tid] = sw[tid];
    __syncthreads();
    const int HW = SIDE * SIDE;
    const int p  = blockIdx.x * 256 + tid;
    if (p >= NB * HW) return;
    const int b  = p / HW, hw = p - b * HW;
    const int y  = hw / SIDE, x = hw - y * SIDE;
    const float* mp = smx + (size_t)b * HW;
    const float* ap = sav + (size_t)b * HW;
    float acc = 0.0f;
#pragma unroll
    for (int dy = -3; dy <= 3; dy++) {
        int yy = y + dy;
        if (yy < 0 || yy >= SIDE) continue;
#pragma unroll
        for (int dx = -3; dx <= 3; dx++) {
            int xx = x + dx;
            if (xx < 0 || xx >= SIDE) continue;
            int wi = (dy + 3) * 7 + (dx + 3);
            int q  = yy * SIDE + xx;
            acc += mp[q] * w[wi] + ap[q] * w[49 + wi];
        }
    }
    S[p] = acc;
}

// ---------------- gather ----------------
__global__ void gather_out(const int* __restrict__ idx, float* __restrict__ out) {
    const int row = blockIdx.x;
    const int c   = threadIdx.x;
    const int b   = row / KIDX;
    const int id  = idx[row];
    const float* Y; const float* S; int HW, scale, p;
    if (id < HW_0)              { Y = g_y0s0; S = g_s0; HW = HW_0; scale = 0; p = id; }
    else if (id < HW_0 + HW_1)  { Y = g_y0s1; S = g_s1; HW = HW_1; scale = 1; p = id - HW_0; }
    else                        { Y = g_y0s2; S = g_s2; HW = HW_2; scale = 2; p = id - (HW_0 + HW_1); }
    float y   = Y[((size_t)b * HW + p) * C_EMB + c];
    float g   = g_gate[(scale * NB + b) * C_EMB + c];
    float sig = sigmoidf_(S[b * HW + p]);
    out[(size_t)row * C_EMB + c] = y * (1.0f + g * sig);
}

// ---------------- launch ----------------
extern "C" void kernel_launch(void* const* d_in, const int* in_sizes, int n_in,
                              void* d_out, int out_size) {
    const float* x0   = (const float*)d_in[0];
    const float* x1   = (const float*)d_in[1];
    const float* x2   = (const float*)d_in[2];
    const float* yolo = (const float*)d_in[3];
    const int*   ridx = (const int*)d_in[4];
    const float* nw0 = (const float*)d_in[5];
    const float* nb0 = (const float*)d_in[6];
    const float* nw1 = (const float*)d_in[7];
    const float* nb1 = (const float*)d_in[8];
    const float* nw2 = (const float*)d_in[9];
    const float* nb2 = (const float*)d_in[10];
    const float* cw1[3] = {(const float*)d_in[11], (const float*)d_in[16], (const float*)d_in[21]};
    const float* cb1[3] = {(const float*)d_in[12], (const float*)d_in[17], (const float*)d_in[22]};
    const float* cw2[3] = {(const float*)d_in[13], (const float*)d_in[18], (const float*)d_in[23]};
    const float* cb2[3] = {(const float*)d_in[14], (const float*)d_in[19], (const float*)d_in[24]};
    const float* csw[3] = {(const float*)d_in[15], (const float*)d_in[20], (const float*)d_in[25]};

    float* out = (float*)d_out;
    const int yolo_n = NB * 8400 * 6;
    const int emb_n  = NB * KIDX * C_EMB;
    float* emb_out = out;
    if (out_size >= yolo_n + emb_n) {
        cudaMemcpyAsync(out, yolo, (size_t)in_sizes[3] * sizeof(float),
                        cudaMemcpyDeviceToDevice, 0);
        emb_out = out + yolo_n;
    }

    float *y0p, *y1p, *y2p;
    cudaGetSymbolAddress((void**)&y0p, g_y0s0);
    cudaGetSymbolAddress((void**)&y1p, g_y0s1);
    cudaGetSymbolAddress((void**)&y2p, g_y0s2);
    __half *wh0, *wh1, *wh2;
    cudaGetSymbolAddress((void**)&wh0, g_wh0);
    cudaGetSymbolAddress((void**)&wh1, g_wh1);
    cudaGetSymbolAddress((void**)&wh2, g_wh2);
    float *smx0p, *sav0p, *s0p, *smx1p, *sav1p, *s1p, *smx2p, *sav2p, *s2p;
    cudaGetSymbolAddress((void**)&smx0p, g_smx0);
    cudaGetSymbolAddress((void**)&sav0p, g_sav0);
    cudaGetSymbolAddress((void**)&s0p,   g_s0);
    cudaGetSymbolAddress((void**)&smx1p, g_smx1);
    cudaGetSymbolAddress((void**)&sav1p, g_sav1);
    cudaGetSymbolAddress((void**)&s1p,   g_s1);
    cudaGetSymbolAddress((void**)&smx2p, g_smx2);
    cudaGetSymbolAddress((void**)&sav2p, g_sav2);
    cudaGetSymbolAddress((void**)&s2p,   g_s2);

    cudaFuncSetAttribute((const void*)gemm_all,
                         cudaFuncAttributeMaxDynamicSharedMemorySize, SMEM_GEMM);

    // launch ordering keeps gemm_all as the 5th stream op so ncu (-s 5 -c 1)
    // captures it next round.
    init_stats<<<(3 * NB * C_EMB + 255) / 256, 256>>>();

    convert_w<<<(C_EMB * 256 + 255) / 256, 256>>>(nw0, wh0, C_EMB * 256);
    convert_w2<<<(C_EMB * (512 + 1024) + 255) / 256, 256>>>(
        nw1, wh1, C_EMB * 512, nw2, wh2, C_EMB * 1024);

    gemm_all<<<dim3(67, NB), 256, SMEM_GEMM>>>(
        x0, x1, x2, wh0, wh1, wh2, nb0, nb1, nb2, y0p, y1p, y2p);

    gate_kernel<<<NB, 128>>>(cw1[0], cb1[0], cw2[0], cb2[0], 0, HW_0);
    gate_kernel<<<NB, 128>>>(cw1[1], cb1[1], cw2[1], cb2[1], 1, HW_1);
    gate_kernel<<<NB, 128>>>(cw1[2], cb1[2], cw2[2], cb2[2], 2, HW_2);

    sam_stats<<<NB * HW_0 / 8, 256>>>(y0p, smx0p, sav0p, HW_0, 0);
    sam_stats<<<NB * HW_1 / 8, 256>>>(y1p, smx1p, sav1p, HW_1, 1);
    sam_stats<<<NB * HW_2 / 8, 256>>>(y2p, smx2p, sav2p, HW_2, 2);

    conv7<<<(NB * HW_0 + 255) / 256, 256>>>(smx0p, sav0p, csw[0], s0p, SIDE0);
    conv7<<<(NB * HW_1 + 255) / 256, 256>>>(smx1p, sav1p, csw[1], s1p, SIDE1);
    conv7<<<(NB * HW_2 + 255) / 256, 256>>>(smx2p, sav2p, csw[2], s2p, SIDE2);

    gather_out<<<NB * KIDX, 128>>>(ridx, emb_out);
}

// round 6
// speedup vs baseline: 3.7188x; 1.2278x over previous
#include <cuda_runtime.h>
#include <cuda_fp16.h>
#include <cstdint>
#include <math.h>

// ---------------- problem constants ----------------
#define NB 32
#define C_EMB 128
#define HID 32
#define KIDX 100

#define HW_0 6400
#define HW_1 1600
#define HW_2 400
#define SIDE0 80
#define SIDE1 40
#define SIDE2 20

#define NBHW0 (NB * HW_0)
#define NBHW1 (NB * HW_1)
#define NBHW2 (NB * HW_2)
#define NPIX  (NBHW0 + NBHW1 + NBHW2)   // 268800

// ---------------- device scratch ----------------
__device__ __align__(128) __half g_y0s0[(size_t)NBHW0 * C_EMB];
__device__ __align__(128) __half g_y0s1[(size_t)NBHW1 * C_EMB];
__device__ __align__(128) __half g_y0s2[(size_t)NBHW2 * C_EMB];

__device__ __align__(128) __half g_wh0[C_EMB * 256];
__device__ __align__(128) __half g_wh1[C_EMB * 512];
__device__ __align__(128) __half g_wh2[C_EMB * 1024];

__device__ unsigned g_maxenc[3 * NB * C_EMB];
__device__ float    g_sum[3 * NB * C_EMB];
__device__ float    g_gate[3 * NB * C_EMB];

__device__ float g_smx0[NBHW0], g_sav0[NBHW0], g_s0[NBHW0];
__device__ float g_smx1[NBHW1], g_sav1[NBHW1], g_s1[NBHW1];
__device__ float g_smx2[NBHW2], g_sav2[NBHW2], g_s2[NBHW2];

// ---------------- helpers ----------------
__device__ __forceinline__ uint32_t smem_to_u32(const void* p) {
    uint32_t a;
    asm("{ .reg .u64 t; cvta.to.shared.u64 t, %1; cvt.u32.u64 %0, t; }" : "=r"(a) : "l"(p));
    return a;
}
__device__ __forceinline__ void ldsm_x4(uint32_t* r, uint32_t addr) {
    asm volatile("ldmatrix.sync.aligned.m8n8.x4.shared.b16 {%0,%1,%2,%3}, [%4];"
                 : "=r"(r[0]), "=r"(r[1]), "=r"(r[2]), "=r"(r[3]) : "r"(addr));
}
__device__ __forceinline__ void ldsm_x4_t(uint32_t* r, uint32_t addr) {
    asm volatile("ldmatrix.sync.aligned.m8n8.x4.trans.shared.b16 {%0,%1,%2,%3}, [%4];"
                 : "=r"(r[0]), "=r"(r[1]), "=r"(r[2]), "=r"(r[3]) : "r"(addr));
}
__device__ __forceinline__ void mma_f16(float* d, const uint32_t* a, const uint32_t* b) {
    asm volatile("mma.sync.aligned.m16n8k16.row.col.f32.f16.f16.f32 "
                 "{%0,%1,%2,%3}, {%4,%5,%6,%7}, {%8,%9}, {%0,%1,%2,%3};"
                 : "+f"(d[0]), "+f"(d[1]), "+f"(d[2]), "+f"(d[3])
                 : "r"(a[0]), "r"(a[1]), "r"(a[2]), "r"(a[3]), "r"(b[0]), "r"(b[1]));
}
__device__ __forceinline__ void cp_async16(uint32_t saddr, const void* gptr) {
    asm volatile("cp.async.cg.shared.global [%0], [%1], 16;" :: "r"(saddr), "l"(gptr));
}
#define CP_COMMIT() asm volatile("cp.async.commit_group;" ::: "memory")
#define CP_WAIT0()  asm volatile("cp.async.wait_group 0;"  ::: "memory")

__device__ __forceinline__ unsigned encf(float f) {
    unsigned u = __float_as_uint(f);
    return (u & 0x80000000u) ? ~u : (u | 0x80000000u);
}
__device__ __forceinline__ float decf(unsigned e) {
    return (e & 0x80000000u) ? __uint_as_float(e & 0x7FFFFFFFu) : __uint_as_float(~e);
}
__device__ __forceinline__ float sigmoidf_(float x) { return 1.0f / (1.0f + __expf(-x)); }

// ---------------- init stats ----------------
__global__ void init_stats() {
    int i = blockIdx.x * blockDim.x + threadIdx.x;
    if (i < 3 * NB * C_EMB) { g_maxenc[i] = 0u; g_sum[i] = 0.0f; }
}

// ---------------- weight conversion ----------------
__global__ void convert_w(const float* __restrict__ W, __half* __restrict__ Wh, int n) {
    int i = blockIdx.x * 256 + threadIdx.x;
    if (i < n) Wh[i] = __float2half_rn(W[i]);
}
__global__ void convert_w2(const float* __restrict__ W1, __half* __restrict__ Wh1, int n1,
                           const float* __restrict__ W2, __half* __restrict__ Wh2, int n2) {
    int i = blockIdx.x * 256 + threadIdx.x;
    if (i < n1) Wh1[i] = __float2half_rn(W1[i]);
    else if (i < n1 + n2) Wh2[i - n1] = __float2half_rn(W2[i - n1]);
}

// ---------------- merged HMMA GEMM, fp16, deep pipeline ----------------
// Y[b][hw][m] (fp16) = sum_k W[m][k] * X[b][k][hw] + bias[m]
// CTA tile: 128 hw x 128 ch; K-chunk 64.
// X: fp32 LDG prefetched 2 chunks ahead in regs, converted fp16, double-buffered smem.
// W: cp.async 1 chunk ahead (L2-resident), double-buffered smem.
static constexpr int SM_XB0  = 0;       // 2 x 16 KB
static constexpr int SM_WB0  = 32768;   // 2 x 16 KB
static constexpr int SM_BIAS = 65536;   // 512 B
static constexpr int SM_RED  = 66048;   // 2 KB reduction scratch
static constexpr int SMEM_GEMM = 68096;
static constexpr int CS_STRIDE = 136;   // fp16 C staging row stride (halves)

__global__ void __launch_bounds__(256, 2)
gemm_all(const float* __restrict__ x0, const float* __restrict__ x1, const float* __restrict__ x2,
         const __half* __restrict__ wh0, const __half* __restrict__ wh1, const __half* __restrict__ wh2,
         const float* __restrict__ nb0, const float* __restrict__ nb1, const float* __restrict__ nb2,
         __half* __restrict__ y0, __half* __restrict__ y1, __half* __restrict__ y2) {
    extern __shared__ __align__(128) char smem[];
    const uint32_t sb = smem_to_u32(smem);
    const int tid  = threadIdx.x;
    const int lane = tid & 31;
    const int wid  = tid >> 5;
    const int wm   = wid & 3;
    const int wn   = wid >> 2;
    const int b    = blockIdx.y;

    const float* X; const __half* Wh; const float* bias; __half* Y;
    int CIN, HW, scale, tile;
    int bx = blockIdx.x;
    if (bx < 50)      { tile = bx;      X = x0; Wh = wh0; bias = nb0; Y = y0; CIN = 256;  HW = HW_0; scale = 0; }
    else if (bx < 63) { tile = bx - 50; X = x1; Wh = wh1; bias = nb1; Y = y1; CIN = 512;  HW = HW_1; scale = 1; }
    else              { tile = bx - 63; X = x2; Wh = wh2; bias = nb2; Y = y2; CIN = 1024; HW = HW_2; scale = 2; }
    const int hw0 = tile * 128;
    int nvalid = HW - hw0; if (nvalid > 128) nvalid = 128;
    const int nchunk = CIN >> 6;

    if (tid < 32) ((float4*)(smem + SM_BIAS))[tid] = ((const float4*)bias)[tid];

    const int ti = lane & 7;
    const int gq = lane >> 3;
    const int aKrow = ((gq >> 1) << 3) + ti;
    const int aMsel = (gq & 1) << 3;
    const int bKsel = gq & 1;
    const int bNrow = ((gq >> 1) << 3) + ti;

    uint32_t offA[2];
#pragma unroll
    for (int mt = 0; mt < 2; mt++) {
        int m0 = wm * 32 + mt * 16 + aMsel;
        offA[mt] = (uint32_t)(aKrow * 256 + ((((m0 >> 3) ^ (aKrow & 7)) << 4)));
    }

    float acc[2][8][4];
#pragma unroll
    for (int mt = 0; mt < 2; mt++)
#pragma unroll
        for (int nt = 0; nt < 8; nt++)
#pragma unroll
            for (int r = 0; r < 4; r++) acc[mt][nt][r] = 0.0f;

    const int xr  = tid >> 2;
    const int xc0 = tid & 3;
    const float* xbase = X + ((size_t)b * CIN) * HW + hw0;

    uint2 xpA[8], xpB[8];   // 2-chunk-deep X prefetch (fp16 packed)

#define LDG_X(K0, SET) do { \
        const float* row_ = xbase + (size_t)((K0) + xr) * HW; \
        _Pragma("unroll") \
        for (int i_ = 0; i_ < 8; i_++) { \
            int c4_ = xc0 + 4 * i_; \
            int hwb_ = c4_ * 4; \
            float4 v_ = (hw0 + hwb_ < HW) ? *(const float4*)(row_ + hwb_) \
                                          : make_float4(0.f, 0.f, 0.f, 0.f); \
            __half2 p0_ = __floats2half2_rn(v_.x, v_.y); \
            __half2 p1_ = __floats2half2_rn(v_.z, v_.w); \
            (SET)[i_] = make_uint2(*(uint32_t*)&p0_, *(uint32_t*)&p1_); \
        } \
    } while (0)

#define STS_X(SET, BUF) do { \
        uint32_t base_ = sb + SM_XB0 + (BUF) * 16384; \
        _Pragma("unroll") \
        for (int i_ = 0; i_ < 8; i_++) { \
            int c4_ = xc0 + 4 * i_; \
            uint32_t off_ = (uint32_t)(xr * 256 + ((((c4_ >> 1) ^ (xr & 7)) << 4)) + (c4_ & 1) * 8); \
            asm volatile("st.shared.v2.b32 [%0], {%1, %2};" :: "r"(base_ + off_), "r"((SET)[i_].x), "r"((SET)[i_].y)); \
        } \
    } while (0)

#define CPA_W(K0, BUF) do { \
        uint32_t wb_ = sb + SM_WB0 + (BUF) * 16384; \
        _Pragma("unroll") \
        for (int i_ = 0; i_ < 4; i_++) { \
            int idx_ = tid + i_ * 256; \
            int n_   = idx_ >> 3; \
            int seg_ = idx_ & 7; \
            uint32_t off_ = (uint32_t)(n_ * 128 + ((seg_ ^ (n_ & 7)) << 4)); \
            cp_async16(wb_ + off_, Wh + (size_t)n_ * CIN + (K0) + seg_ * 8); \
        } \
    } while (0)

    // ---- prologue ----
    CPA_W(0, 0);
    CP_COMMIT();
    LDG_X(0, xpA);
    LDG_X(64, xpB);              // nchunk >= 4 always
    STS_X(xpA, 0);
    CP_WAIT0();
    __syncthreads();

    for (int ck = 0; ; ck++) {
        const int cur = ck & 1;
        // W for next chunk (buffer cur^1 is free: sync at end of prev iter)
        if (ck + 1 < nchunk) { CPA_W((ck + 1) * 64, cur ^ 1); CP_COMMIT(); }
        // X for chunk ck+2 into the register set just freed (chunk ck was STS'd)
        if (ck + 2 < nchunk) { if (cur) LDG_X((ck + 2) * 64, xpB); else LDG_X((ck + 2) * 64, xpA); }

        const uint32_t xb = sb + SM_XB0 + cur * 16384;
        const uint32_t wb = sb + SM_WB0 + cur * 16384;
#pragma unroll
        for (int ks = 0; ks < 4; ks++) {
            const uint32_t kb256 = (uint32_t)(ks * 16 * 256);
            uint32_t ah[2][4];
            ldsm_x4_t(ah[0], xb + kb256 + offA[0]);
            ldsm_x4_t(ah[1], xb + kb256 + offA[1]);
#pragma unroll
            for (int np = 0; np < 4; np++) {
                int nrow = wn * 64 + np * 16 + bNrow;
                int kseg = ks * 2 + bKsel;
                uint32_t boff = (uint32_t)(nrow * 128 + (((kseg ^ (nrow & 7)) << 4)));
                uint32_t bh[4];
                ldsm_x4(bh, wb + boff);
#pragma unroll
                for (int mt = 0; mt < 2; mt++)
#pragma unroll
                    for (int s = 0; s < 2; s++)
                        mma_f16(acc[mt][np * 2 + s], ah[mt], &bh[s * 2]);
            }
        }
        if (ck + 1 >= nchunk) break;
        // store chunk ck+1 (held in set (ck+1)&1) into X buffer cur^1
        if (cur) STS_X(xpA, cur ^ 1); else STS_X(xpB, cur ^ 1);
        CP_WAIT0();
        __syncthreads();
    }
    __syncthreads();

    // ---- epilogue: fp16 C staging with bias, coalesced Y store, fused CAM ----
    __half* Cs = (__half*)smem;                       // [128][CS_STRIDE]
    const float* bsm = (const float*)(smem + SM_BIAS);
#pragma unroll
    for (int mt = 0; mt < 2; mt++) {
#pragma unroll
        for (int nt = 0; nt < 8; nt++) {
            int r0 = wm * 32 + mt * 16 + (lane >> 2);
            int c0 = wn * 64 + nt * 8 + (lane & 3) * 2;
            float b0 = bsm[c0], b1 = bsm[c0 + 1];
            __half2 v0 = __floats2half2_rn(acc[mt][nt][0] + b0, acc[mt][nt][1] + b1);
            __half2 v1 = __floats2half2_rn(acc[mt][nt][2] + b0, acc[mt][nt][3] + b1);
            *(__half2*)&Cs[r0 * CS_STRIDE + c0]       = v0;
            *(__half2*)&Cs[(r0 + 8) * CS_STRIDE + c0] = v1;
        }
    }
    __syncthreads();

    __half* yb = Y + ((size_t)b * HW + hw0) * C_EMB;
    for (int idx = tid; idx < nvalid * 16; idx += 256) {
        int r = idx >> 4;
        int s = idx & 15;
        uint4 v = *(const uint4*)&Cs[r * CS_STRIDE + s * 8];
        *(uint4*)&yb[(size_t)r * C_EMB + s * 8] = v;
    }
    // CAM stats: 2 threads per channel
    {
        float* redm = (float*)(smem + SM_RED);
        float* reds = redm + 256;
        int c = tid & 127, h = tid >> 7;
        int rs = h ? (nvalid + 1) / 2 : 0;
        int re = h ? nvalid : (nvalid + 1) / 2;
        float mx = -3.4e38f, sm = 0.0f;
        for (int r = rs; r < re; r++) {
            float v = __half2float(Cs[r * CS_STRIDE + c]);
            mx = fmaxf(mx, v);
            sm += v;
        }
        redm[tid] = mx; reds[tid] = sm;
        __syncthreads();
        if (tid < 128) {
            mx = fmaxf(redm[tid], redm[tid + 128]);
            sm = reds[tid] + reds[tid + 128];
            int o = (scale * NB + b) * C_EMB + tid;
            atomicMax(&g_maxenc[o], encf(mx));
            atomicAdd(&g_sum[o], sm);
        }
    }
}

// ---------------- merged gate ----------------
__global__ void gate_all(const float* __restrict__ w1a, const float* __restrict__ b1a,
                         const float* __restrict__ w2a, const float* __restrict__ b2a,
                         const float* __restrict__ w1b, const float* __restrict__ b1b,
                         const float* __restrict__ w2b, const float* __restrict__ b2b,
                         const float* __restrict__ w1c, const float* __restrict__ b1c,
                         const float* __restrict__ w2c, const float* __restrict__ b2c) {
    __shared__ float vmx[C_EMB], vav[C_EMB], hmx[HID], hav[HID];
    const int scale = blockIdx.x >> 5;
    const int b = blockIdx.x & 31;
    const int c = threadIdx.x;
    const float* w1; const float* b1; const float* w2; const float* b2; int HW;
    if (scale == 0)      { w1 = w1a; b1 = b1a; w2 = w2a; b2 = b2a; HW = HW_0; }
    else if (scale == 1) { w1 = w1b; b1 = b1b; w2 = w2b; b2 = b2b; HW = HW_1; }
    else                 { w1 = w1c; b1 = b1c; w2 = w2c; b2 = b2c; HW = HW_2; }
    const int o = (scale * NB + b) * C_EMB + c;
    vmx[c] = decf(g_maxenc[o]);
    vav[c] = g_sum[o] * (1.0f / (float)HW);
    __syncthreads();
    if (c < HID) {
        float s1 = b1[c], s2 = b1[c];
        for (int k = 0; k < C_EMB; k++) {
            float w = w1[c * C_EMB + k];
            s1 += w * vmx[k];
            s2 += w * vav[k];
        }
        hmx[c] = fmaxf(s1, 0.0f);
        hav[c] = fmaxf(s2, 0.0f);
    }
    __syncthreads();
    float o1 = b2[c], o2 = b2[c];
    for (int k = 0; k < HID; k++) {
        float w = w2[c * HID + k];
        o1 += w * hmx[k];
        o2 += w * hav[k];
    }
    g_gate[o] = sigmoidf_(o1 + o2);
}

// ---------------- merged SAM stats (fp16 Y) ----------------
__global__ void sam_all(const __half* __restrict__ y0, const __half* __restrict__ y1,
                        const __half* __restrict__ y2,
                        float* __restrict__ smx0, float* __restrict__ sav0,
                        float* __restrict__ smx1, float* __restrict__ sav1,
                        float* __restrict__ smx2, float* __restrict__ sav2) {
    const int gw   = blockIdx.x * 8 + (threadIdx.x >> 5);
    const int lane = threadIdx.x & 31;
    const __half* Y; float* smx; float* sav; int HW, scale, pix;
    if (gw < NBHW0)                { Y = y0; smx = smx0; sav = sav0; HW = HW_0; scale = 0; pix = gw; }
    else if (gw < NBHW0 + NBHW1)   { Y = y1; smx = smx1; sav = sav1; HW = HW_1; scale = 1; pix = gw - NBHW0; }
    else                           { Y = y2; smx = smx2; sav = sav2; HW = HW_2; scale = 2; pix = gw - NBHW0 - NBHW1; }
    const int b = pix / HW;
    float4 g = *(const float4*)&g_gate[(scale * NB + b) * C_EMB + lane * 4];
    uint2 raw = *(const uint2*)&Y[(size_t)pix * C_EMB + lane * 4];
    __half2 h0 = *(__half2*)&raw.x;
    __half2 h1 = *(__half2*)&raw.y;
    float a0 = __half2float(h0.x) * g.x, a1 = __half2float(h0.y) * g.y;
    float a2 = __half2float(h1.x) * g.z, a3 = __half2float(h1.y) * g.w;
    float mx = fmaxf(fmaxf(a0, a1), fmaxf(a2, a3));
    float sm = a0 + a1 + a2 + a3;
#pragma unroll
    for (int o = 16; o; o >>= 1) {
        mx = fmaxf(mx, __shfl_xor_sync(0xFFFFFFFFu, mx, o));
        sm += __shfl_xor_sync(0xFFFFFFFFu, sm, o);
    }
    if (lane == 0) {
        smx[pix] = mx;
        sav[pix] = sm * (1.0f / (float)C_EMB);
    }
}

// ---------------- merged 7x7 conv ----------------
__global__ void conv7_all(const float* __restrict__ sw0, const float* __restrict__ sw1,
                          const float* __restrict__ sw2) {
    __shared__ float w[3][98];
    const int tid = threadIdx.x;
    for (int i = tid; i < 294; i += 256) {
        int s = i / 98, j = i - s * 98;
        const float* src = (s == 0) ? sw0 : (s == 1) ? sw1 : sw2;
        w[s][j] = src[j];
    }
    __syncthreads();
    const int p = blockIdx.x * 256 + tid;
    if (p >= NPIX) return;
    const float* smx; const float* sav; float* S; int HW, SIDE, scale, pix;
    if (p < NBHW0)               { smx = g_smx0; sav = g_sav0; S = g_s0; HW = HW_0; SIDE = SIDE0; scale = 0; pix = p; }
    else if (p < NBHW0 + NBHW1)  { smx = g_smx1; sav = g_sav1; S = g_s1; HW = HW_1; SIDE = SIDE1; scale = 1; pix = p - NBHW0; }
    else                         { smx = g_smx2; sav = g_sav2; S = g_s2; HW = HW_2; SIDE = SIDE2; scale = 2; pix = p - NBHW0 - NBHW1; }
    const int b  = pix / HW, hw = pix - b * HW;
    const int y  = hw / SIDE, x = hw - y * SIDE;
    const float* mp = smx + (size_t)b * HW;
    const float* ap = sav + (size_t)b * HW;
    const float* wm = w[scale];
    float acc = 0.0f;
#pragma unroll
    for (int dy = -3; dy <= 3; dy++) {
        int yy = y + dy;
        if (yy < 0 || yy >= SIDE) continue;
#pragma unroll
        for (int dx = -3; dx <= 3; dx++) {
            int xx = x + dx;
            if (xx < 0 || xx >= SIDE) continue;
            int wi = (dy + 3) * 7 + (dx + 3);
            int q  = yy * SIDE + xx;
            acc += mp[q] * wm[wi] + ap[q] * wm[49 + wi];
        }
    }
    S[pix] = acc;
}

// ---------------- gather ----------------
__global__ void gather_out(const int* __restrict__ idx, float* __restrict__ out) {
    const int row = blockIdx.x;
    const int c   = threadIdx.x;
    const int b   = row / KIDX;
    const int id  = idx[row];
    const __half* Y; const float* S; int HW, scale, p;
    if (id < HW_0)              { Y = g_y0s0; S = g_s0; HW = HW_0; scale = 0; p = id; }
    else if (id < HW_0 + HW_1)  { Y = g_y0s1; S = g_s1; HW = HW_1; scale = 1; p = id - HW_0; }
    else                        { Y = g_y0s2; S = g_s2; HW = HW_2; scale = 2; p = id - (HW_0 + HW_1); }
    float y   = __half2float(Y[((size_t)b * HW + p) * C_EMB + c]);
    float g   = g_gate[(scale * NB + b) * C_EMB + c];
    float sig = sigmoidf_(S[b * HW + p]);
    out[(size_t)row * C_EMB + c] = y * (1.0f + g * sig);
}

// ---------------- launch ----------------
extern "C" void kernel_launch(void* const* d_in, const int* in_sizes, int n_in,
                              void* d_out, int out_size) {
    const float* x0   = (const float*)d_in[0];
    const float* x1   = (const float*)d_in[1];
    const float* x2   = (const float*)d_in[2];
    const float* yolo = (const float*)d_in[3];
    const int*   ridx = (const int*)d_in[4];
    const float* nw0 = (const float*)d_in[5];
    const float* nb0 = (const float*)d_in[6];
    const float* nw1 = (const float*)d_in[7];
    const float* nb1 = (const float*)d_in[8];
    const float* nw2 = (const float*)d_in[9];
    const float* nb2 = (const float*)d_in[10];
    const float* cw1[3] = {(const float*)d_in[11], (const float*)d_in[16], (const float*)d_in[21]};
    const float* cb1[3] = {(const float*)d_in[12], (const float*)d_in[17], (const float*)d_in[22]};
    const float* cw2[3] = {(const float*)d_in[13], (const float*)d_in[18], (const float*)d_in[23]};
    const float* cb2[3] = {(const float*)d_in[14], (const float*)d_in[19], (const float*)d_in[24]};
    const float* csw[3] = {(const float*)d_in[15], (const float*)d_in[20], (const float*)d_in[25]};

    float* out = (float*)d_out;
    const int yolo_n = NB * 8400 * 6;
    const int emb_n  = NB * KIDX * C_EMB;
    float* emb_out = out;
    if (out_size >= yolo_n + emb_n) {
        cudaMemcpyAsync(out, yolo, (size_t)in_sizes[3] * sizeof(float),
                        cudaMemcpyDeviceToDevice, 0);
        emb_out = out + yolo_n;
    }

    __half *y0p, *y1p, *y2p;
    cudaGetSymbolAddress((void**)&y0p, g_y0s0);
    cudaGetSymbolAddress((void**)&y1p, g_y0s1);
    cudaGetSymbolAddress((void**)&y2p, g_y0s2);
    __half *wh0, *wh1, *wh2;
    cudaGetSymbolAddress((void**)&wh0, g_wh0);
    cudaGetSymbolAddress((void**)&wh1, g_wh1);
    cudaGetSymbolAddress((void**)&wh2, g_wh2);
    float *smx0p, *sav0p, *smx1p, *sav1p, *smx2p, *sav2p;
    cudaGetSymbolAddress((void**)&smx0p, g_smx0);
    cudaGetSymbolAddress((void**)&sav0p, g_sav0);
    cudaGetSymbolAddress((void**)&smx1p, g_smx1);
    cudaGetSymbolAddress((void**)&sav1p, g_sav1);
    cudaGetSymbolAddress((void**)&smx2p, g_smx2);
    cudaGetSymbolAddress((void**)&sav2p, g_sav2);

    cudaFuncSetAttribute((const void*)gemm_all,
                         cudaFuncAttributeMaxDynamicSharedMemorySize, SMEM_GEMM);

    init_stats<<<(3 * NB * C_EMB + 255) / 256, 256>>>();
    convert_w<<<(C_EMB * 256 + 255) / 256, 256>>>(nw0, wh0, C_EMB * 256);
    convert_w2<<<(C_EMB * (512 + 1024) + 255) / 256, 256>>>(
        nw1, wh1, C_EMB * 512, nw2, wh2, C_EMB * 1024);

    gemm_all<<<dim3(67, NB), 256, SMEM_GEMM>>>(
        x0, x1, x2, wh0, wh1, wh2, nb0, nb1, nb2, y0p, y1p, y2p);

    gate_all<<<96, 128>>>(cw1[0], cb1[0], cw2[0], cb2[0],
                          cw1[1], cb1[1], cw2[1], cb2[1],
                          cw1[2], cb1[2], cw2[2], cb2[2]);

    sam_all<<<NPIX / 8, 256>>>(y0p, y1p, y2p, smx0p, sav0p, smx1p, sav1p, smx2p, sav2p);

    conv7_all<<<(NPIX + 255) / 256, 256>>>(csw[0], csw[1], csw[2]);

    gather_out<<<NB * KIDX, 128>>>(ridx, emb_out);
}